// round 2
// baseline (speedup 1.0000x reference)
#include <cuda_runtime.h>
#include <cuda_bf16.h>
#include <math.h>

// Problem constants
#define BB 4
#define NN 4096
#define MM 4096
#define EE 512
#define HH 8
#define DD 64
#define ROWS_QK (BB * NN)        // 16384
#define ROWS_MLP (BB * MM * HH)  // 131072

// ---------------- scratch (device globals; no allocation) ----------------
__device__ float g_q[ROWS_QK * EE];     // elu(query@Wq)+1
__device__ float g_k[ROWS_QK * EE];     // elu(key@Wk)+1
__device__ float g_v[ROWS_QK * EE];     // value@Wv
__device__ float g_h1[ROWS_MLP * 128];  // gelu hidden
__device__ float g_ka[ROWS_QK * EE];    // elu(mlp)+1  (viewed as [B*M*H, 64])
__device__ float g_kv[BB * HH * DD * DD];
__device__ float g_ksum[BB * HH * DD];
__device__ float g_attn[ROWS_QK * EE];

// ---------------- generic register-tiled SGEMM ----------------
// C[M_,N_] = epi(A[M_,K_] @ W[K_,N_] + bias[N_])
// EPI: 0 = none, 1 = elu(x)+1, 2 = exact gelu
template <int BM, int BN, int BK, int TM, int TN, int EPI>
__global__ void sgemm_kernel(const float* __restrict__ A,
                             const float* __restrict__ W,
                             const float* __restrict__ bias,
                             float* __restrict__ C,
                             int M_, int N_, int K_) {
    constexpr int NT = (BM / TM) * (BN / TN);
    __shared__ float As[BK][BM + 4];
    __shared__ float Bs[BK][BN];

    const int tid = threadIdx.x;
    const int tx = tid % (BN / TN);
    const int ty = tid / (BN / TN);
    const int row0 = blockIdx.y * BM;
    const int col0 = blockIdx.x * BN;

    float acc[TM][TN];
#pragma unroll
    for (int i = 0; i < TM; i++)
#pragma unroll
        for (int j = 0; j < TN; j++) acc[i][j] = 0.f;

    for (int k0 = 0; k0 < K_; k0 += BK) {
        // A tile: BM x BK, stored transposed
#pragma unroll
        for (int i = tid; i < BM * BK / 4; i += NT) {
            int m = i / (BK / 4);
            int k4 = i % (BK / 4);
            float4 val = *(const float4*)&A[(size_t)(row0 + m) * K_ + k0 + k4 * 4];
            As[k4 * 4 + 0][m] = val.x;
            As[k4 * 4 + 1][m] = val.y;
            As[k4 * 4 + 2][m] = val.z;
            As[k4 * 4 + 3][m] = val.w;
        }
        // B tile: BK x BN
#pragma unroll
        for (int i = tid; i < BK * BN / 4; i += NT) {
            int kk = i / (BN / 4);
            int n4 = i % (BN / 4);
            *(float4*)&Bs[kk][n4 * 4] =
                *(const float4*)&W[(size_t)(k0 + kk) * N_ + col0 + n4 * 4];
        }
        __syncthreads();

#pragma unroll
        for (int kk = 0; kk < BK; kk++) {
            float regM[TM], regN[TN];
#pragma unroll
            for (int i = 0; i < TM; i++) regM[i] = As[kk][ty * TM + i];
#pragma unroll
            for (int j = 0; j < TN; j++) regN[j] = Bs[kk][tx * TN + j];
#pragma unroll
            for (int i = 0; i < TM; i++)
#pragma unroll
                for (int j = 0; j < TN; j++) acc[i][j] += regM[i] * regN[j];
        }
        __syncthreads();
    }

#pragma unroll
    for (int i = 0; i < TM; i++) {
        int r = row0 + ty * TM + i;
#pragma unroll
        for (int j = 0; j < TN; j++) {
            int c = col0 + tx * TN + j;
            float v = acc[i][j] + bias[c];
            if (EPI == 1) {
                v = (v > 0.f) ? (v + 1.f) : expf(v);
            } else if (EPI == 2) {
                v = 0.5f * v * (1.f + erff(v * 0.70710678118654752f));
            }
            C[(size_t)r * N_ + c] = v;
        }
    }
}

// ---------------- zero kv/ksum accumulators ----------------
__global__ void zero_kernel(float* __restrict__ kv, float* __restrict__ ksum) {
    int i = blockIdx.x * blockDim.x + threadIdx.x;
    int nkv = BB * HH * DD * DD;
    if (i < nkv) kv[i] = 0.f;
    if (i < BB * HH * DD) ksum[i] = 0.f;
}

// ---------------- kv_context: per (b,h) 64x64 = ka^T @ v over m, split-K ----
__global__ void kv_kernel(const float* __restrict__ ka, const float* __restrict__ v,
                          float* __restrict__ kv) {
    const int bh = blockIdx.x;          // 0..31
    const int b = bh / HH, h = bh % HH;
    const int m0 = blockIdx.y * 256;    // 16 chunks of 256
    __shared__ float ka_s[16][64];
    __shared__ float v_s[16][64];

    const int tid = threadIdx.x;        // 256 threads
    const int tx = tid % 16, ty = tid / 16;
    float acc[4][4];
#pragma unroll
    for (int i = 0; i < 4; i++)
#pragma unroll
        for (int j = 0; j < 4; j++) acc[i][j] = 0.f;

    const size_t base = (size_t)b * MM * EE + (size_t)h * DD;
    for (int mt = 0; mt < 16; mt++) {
        const int m = m0 + mt * 16;
        {
            int mm = tid / 16;
            int e4 = tid % 16;
            size_t g = base + (size_t)(m + mm) * EE + e4 * 4;
            *(float4*)&ka_s[mm][e4 * 4] = *(const float4*)&ka[g];
            *(float4*)&v_s[mm][e4 * 4] = *(const float4*)&v[g];
        }
        __syncthreads();
#pragma unroll
        for (int mm = 0; mm < 16; mm++) {
            float rd[4];
            float4 re = *(const float4*)&v_s[mm][tx * 4];
#pragma unroll
            for (int i = 0; i < 4; i++) rd[i] = ka_s[mm][ty * 4 + i];
            acc[0][0] += rd[0] * re.x; acc[0][1] += rd[0] * re.y;
            acc[0][2] += rd[0] * re.z; acc[0][3] += rd[0] * re.w;
            acc[1][0] += rd[1] * re.x; acc[1][1] += rd[1] * re.y;
            acc[1][2] += rd[1] * re.z; acc[1][3] += rd[1] * re.w;
            acc[2][0] += rd[2] * re.x; acc[2][1] += rd[2] * re.y;
            acc[2][2] += rd[2] * re.z; acc[2][3] += rd[2] * re.w;
            acc[3][0] += rd[3] * re.x; acc[3][1] += rd[3] * re.y;
            acc[3][2] += rd[3] * re.z; acc[3][3] += rd[3] * re.w;
        }
        __syncthreads();
    }
    const float inv_m = 1.f / (float)MM;
#pragma unroll
    for (int i = 0; i < 4; i++)
#pragma unroll
        for (int j = 0; j < 4; j++)
            atomicAdd(&kv[((size_t)bh * DD + ty * 4 + i) * DD + tx * 4 + j],
                      acc[i][j] * inv_m);
}

// ---------------- k_sum: per (b,h,d) reduce over m, split over m ----------
__global__ void ksum_kernel(const float* __restrict__ ka, float* __restrict__ ksum) {
    const int bh = blockIdx.x;
    const int b = bh / HH, h = bh % HH;
    const int m0 = blockIdx.y * 512;
    const int d = threadIdx.x;  // 64
    float s = 0.f;
    const size_t base = (size_t)b * MM * EE + (size_t)h * DD + d;
    for (int m = 0; m < 512; m++) s += ka[base + (size_t)(m0 + m) * EE];
    atomicAdd(&ksum[bh * DD + d], s * (1.f / (float)MM));
}

// ---------------- out: attn[b,n,h,e] = (q . kv) / clip(q . ksum) ----------
#define OUT_ROWS 32
__global__ void out_kernel(const float* __restrict__ q, const float* __restrict__ kv,
                           const float* __restrict__ ksum, float* __restrict__ attn) {
    extern __shared__ float sm[];
    float* kv_s = sm;                 // [8][64][64]
    float* ks_s = sm + HH * DD * DD;  // [8][64]
    const int b = blockIdx.x;
    const int r0 = blockIdx.y * OUT_ROWS;
    const int tid = threadIdx.x;      // 256

    for (int i = tid; i < HH * DD * DD / 4; i += 256)
        *(float4*)&kv_s[i * 4] = *(const float4*)&kv[(size_t)b * HH * DD * DD + i * 4];
    for (int i = tid; i < HH * DD / 4; i += 256)
        *(float4*)&ks_s[i * 4] = *(const float4*)&ksum[b * HH * DD + i * 4];
    __syncthreads();

    const int h = tid / 32, lane = tid % 32;
    const float* kvh = &kv_s[h * DD * DD];

    for (int r = 0; r < OUT_ROWS; r++) {
        const int n = r0 + r;
        const size_t qb = ((size_t)b * NN + n) * EE + h * DD;
        float q0 = q[qb + lane];
        float q1 = q[qb + lane + 32];
        // denominator
        float dp = q0 * ks_s[h * DD + lane] + q1 * ks_s[h * DD + lane + 32];
#pragma unroll
        for (int off = 16; off; off >>= 1) dp += __shfl_xor_sync(0xffffffffu, dp, off);
        dp = fmaxf(dp, 1e-6f);
        float a0 = 0.f, a1 = 0.f;
#pragma unroll
        for (int d = 0; d < DD; d++) {
            float qd = __shfl_sync(0xffffffffu, (d < 32) ? q0 : q1, d & 31);
            float2 kvv = *(const float2*)&kvh[d * DD + lane * 2];
            a0 += qd * kvv.x;
            a1 += qd * kvv.y;
        }
        a0 /= dp;
        a1 /= dp;
        a0 = isnan(a0) ? 0.f : fminf(fmaxf(a0, -65000.f), 65000.f);
        a1 = isnan(a1) ? 0.f : fminf(fmaxf(a1, -65000.f), 65000.f);
        float2 o = make_float2(a0, a1);
        *(float2*)&attn[qb + lane * 2] = o;
    }
}

// ---------------- launch ----------------
extern "C" void kernel_launch(void* const* d_in, const int* in_sizes, int n_in,
                              void* d_out, int out_size) {
    const float* query = (const float*)d_in[0];
    const float* key   = (const float*)d_in[1];
    const float* value = (const float*)d_in[2];
    const float* Wq = (const float*)d_in[3];
    const float* bq = (const float*)d_in[4];
    const float* Wk = (const float*)d_in[5];
    const float* bk = (const float*)d_in[6];
    const float* Wv = (const float*)d_in[7];
    const float* bv = (const float*)d_in[8];
    const float* W1 = (const float*)d_in[9];
    const float* b1 = (const float*)d_in[10];
    const float* W2 = (const float*)d_in[11];
    const float* b2 = (const float*)d_in[12];
    const float* Wo = (const float*)d_in[13];
    const float* bo = (const float*)d_in[14];
    float* out = (float*)d_out;

    float *q_s, *k_s, *v_s, *h1_s, *ka_s, *kv_s, *ksum_s, *attn_s;
    cudaGetSymbolAddress((void**)&q_s, g_q);
    cudaGetSymbolAddress((void**)&k_s, g_k);
    cudaGetSymbolAddress((void**)&v_s, g_v);
    cudaGetSymbolAddress((void**)&h1_s, g_h1);
    cudaGetSymbolAddress((void**)&ka_s, g_ka);
    cudaGetSymbolAddress((void**)&kv_s, g_kv);
    cudaGetSymbolAddress((void**)&ksum_s, g_ksum);
    cudaGetSymbolAddress((void**)&attn_s, g_attn);

    // ---- projections: [16384,512] @ [512,512]
    {
        dim3 grid(EE / 128, ROWS_QK / 128);
        sgemm_kernel<128, 128, 16, 8, 8, 1><<<grid, 256>>>(query, Wq, bq, q_s, ROWS_QK, EE, EE);
        sgemm_kernel<128, 128, 16, 8, 8, 1><<<grid, 256>>>(key,   Wk, bk, k_s, ROWS_QK, EE, EE);
        sgemm_kernel<128, 128, 16, 8, 8, 0><<<grid, 256>>>(value, Wv, bv, v_s, ROWS_QK, EE, EE);
    }
    // ---- per-head MLP on keys: view g_k as [131072, 64]
    {
        dim3 grid1(128 / 128, ROWS_MLP / 128);
        sgemm_kernel<128, 128, 16, 8, 8, 2><<<grid1, 256>>>(k_s, W1, b1, h1_s, ROWS_MLP, 128, 64);
        dim3 grid2(64 / 64, ROWS_MLP / 128);
        sgemm_kernel<128, 64, 16, 8, 8, 1><<<grid2, 128>>>(h1_s, W2, b2, ka_s, ROWS_MLP, 64, 128);
    }
    // ---- kv context + ksum (split-K with atomics into zeroed buffers)
    {
        int nz = BB * HH * DD * DD;
        zero_kernel<<<(nz + 255) / 256, 256>>>(kv_s, ksum_s);
        dim3 gkv(BB * HH, MM / 256);
        kv_kernel<<<gkv, 256>>>(ka_s, v_s, kv_s);
        dim3 gks(BB * HH, MM / 512);
        ksum_kernel<<<gks, 64>>>(ka_s, ksum_s);
    }
    // ---- out einsum + normalize (kv cached in 130KB smem)
    {
        size_t smem = (size_t)(HH * DD * DD + HH * DD) * sizeof(float);
        cudaFuncSetAttribute(out_kernel, cudaFuncAttributeMaxDynamicSharedMemorySize,
                             (int)smem);
        dim3 go(BB, NN / OUT_ROWS);
        out_kernel<<<go, 256, smem>>>(q_s, kv_s, ksum_s, attn_s);
    }
    // ---- final projection: attn @ Wo + bo -> d_out
    {
        dim3 grid(EE / 128, ROWS_QK / 128);
        sgemm_kernel<128, 128, 16, 8, 8, 0><<<grid, 256>>>(attn_s, Wo, bo, out, ROWS_QK, EE, EE);
    }
}

// round 4
// speedup vs baseline: 1.8139x; 1.8139x over previous
#include <cuda_runtime.h>
#include <cuda_bf16.h>
#include <math.h>
#include <stdint.h>

#define BB 4
#define NN 4096
#define MMCTX 4096
#define EE 512
#define HH 8
#define DD 64
#define ROWS_QK (BB * NN)          // 16384
#define ROWS_MLP (BB * MMCTX * HH) // 131072

typedef __nv_bfloat16 bf16;
typedef __nv_bfloat162 bf162;

__device__ __forceinline__ uint32_t smem_u32(const void* p) {
    uint32_t a;
    asm("{ .reg .u64 t; cvta.to.shared.u64 t, %1; cvt.u32.u64 %0, t; }"
        : "=r"(a) : "l"(p));
    return a;
}

#define SWZ128(b) ((b) ^ (((b) >> 3) & 0x70))

__device__ __forceinline__ void cp_async16(uint32_t dst, const void* src) {
    asm volatile("cp.async.cg.shared.global [%0], [%1], 16;\n"
                 :: "r"(dst), "l"(src));
}
#define CP_COMMIT() asm volatile("cp.async.commit_group;\n" ::: "memory")
#define CP_WAIT1() asm volatile("cp.async.wait_group 1;\n" ::: "memory")
#define CP_WAIT0() asm volatile("cp.async.wait_group 0;\n" ::: "memory")

__device__ __forceinline__ void ldmatrix_x4(uint32_t addr, uint32_t& r0,
                                            uint32_t& r1, uint32_t& r2,
                                            uint32_t& r3) {
    asm volatile("ldmatrix.sync.aligned.m8n8.x4.shared.b16 {%0,%1,%2,%3}, [%4];"
                 : "=r"(r0), "=r"(r1), "=r"(r2), "=r"(r3) : "r"(addr));
}

__device__ __forceinline__ void mma16816(float* c, const uint32_t* a,
                                         const uint32_t* b) {
    asm volatile(
        "mma.sync.aligned.m16n8k16.row.col.f32.bf16.bf16.f32 "
        "{%0,%1,%2,%3}, {%4,%5,%6,%7}, {%8,%9}, {%0,%1,%2,%3};"
        : "+f"(c[0]), "+f"(c[1]), "+f"(c[2]), "+f"(c[3])
        : "r"(a[0]), "r"(a[1]), "r"(a[2]), "r"(a[3]), "r"(b[0]), "r"(b[1]));
}

// ===================== scratch =====================
__device__ float g_q[ROWS_QK * EE];
__device__ float g_v[ROWS_QK * EE];
__device__ float g_ka[ROWS_MLP * DD];
__device__ float g_kv[BB * HH * DD * DD];
__device__ float g_ksum[BB * HH * DD];

__device__ bf16 g_qin_ext[ROWS_QK * 3 * EE];
__device__ bf16 g_kin_ext[ROWS_QK * 3 * EE];
__device__ bf16 g_vin_ext[ROWS_QK * 3 * EE];
__device__ bf16 g_kact_ext[ROWS_MLP * 3 * DD];
__device__ bf16 g_h1_ext[ROWS_MLP * 3 * 128];
__device__ bf16 g_attn_ext[ROWS_QK * 3 * EE];

__device__ bf16 g_Wq_ext[EE * 3 * EE];
__device__ bf16 g_Wk_ext[EE * 3 * EE];
__device__ bf16 g_Wv_ext[EE * 3 * EE];
__device__ bf16 g_Wo_ext[EE * 3 * EE];
__device__ bf16 g_W1_ext[128 * 3 * 64];
__device__ bf16 g_W2_ext[64 * 3 * 128];

// ===================== conversions =====================
// A-ext row layout: [hi(K) | lo(K) | hi(K)]
__global__ void conv_act_ext(const float* __restrict__ x, bf16* __restrict__ ext,
                             int n, int K) {
    int i = blockIdx.x * blockDim.x + threadIdx.x;
    if (i >= n) return;
    int r = i / K, k = i % K;
    float v = x[i];
    bf16 h = __float2bfloat16(v);
    bf16 l = __float2bfloat16(v - __bfloat162float(h));
    size_t base = (size_t)r * 3 * K;
    ext[base + k] = h;
    ext[base + K + k] = l;
    ext[base + 2 * K + k] = h;
}

// W[k*N+n] -> Bext[n][3K] layout: [hi(K) | hi(K) | lo(K)]
__global__ void conv_wt_ext(const float* __restrict__ W, bf16* __restrict__ ext,
                            int K, int N) {
    int idx = blockIdx.x * blockDim.x + threadIdx.x;
    if (idx >= K * N) return;
    int k = idx / N, n = idx % N;
    float v = W[idx];
    bf16 h = __float2bfloat16(v);
    bf16 l = __float2bfloat16(v - __bfloat162float(h));
    size_t base = (size_t)n * 3 * K;
    ext[base + k] = h;
    ext[base + K + k] = h;
    ext[base + 2 * K + k] = l;
}

// ===================== HMMA GEMM =====================
// C[M,N] = epi(A @ W + bias); A: [M,Kext] bf16 row-major (ext),
// B: [N,Kext] bf16 row-major. EPI: 0 none, 1 elu+1, 2 gelu.
// OUTM: 0 -> Cf fp32 [M,Ntot]; 1 -> Cext in consumer A-ext layout with chunk CK.
template <int BN, int EPI, int OUTM>
__global__ void __launch_bounds__(256)
mma_gemm(const bf16* __restrict__ A, const bf16* __restrict__ B,
         const float* __restrict__ bias, float* __restrict__ Cf,
         bf16* __restrict__ Cext, int Ntot, int Kext, int CK) {
    extern __shared__ char sm[];
    constexpr int STAGE = (128 + BN) * 128;  // bytes
    constexpr int NT = (BN == 128) ? 8 : 4;  // n-tiles per warp
    constexpr int WNW = NT * 8;              // warp n width

    const int tid = threadIdx.x;
    const int lane = tid & 31, wid = tid >> 5;
    const int wm = wid >> 1, wn = wid & 1;
    const int row0 = blockIdx.y * 128;
    const int col0 = blockIdx.x * BN;
    const uint32_t smb = smem_u32(sm);
    const int nc = Kext / 64;

    float acc[2][NT][4];
#pragma unroll
    for (int i = 0; i < 2; i++)
#pragma unroll
        for (int j = 0; j < NT; j++)
#pragma unroll
            for (int t = 0; t < 4; t++) acc[i][j][t] = 0.f;

    // stage loader
    auto load_stage = [&](int c, int buf) {
        uint32_t as = smb + buf * STAGE;
        uint32_t bs = as + 128 * 128;
        const bf16* Ap = A + (size_t)row0 * Kext + c * 64;
        const bf16* Bp = B + (size_t)col0 * Kext + c * 64;
#pragma unroll
        for (int i = 0; i < 4; i++) {
            int idx = tid + i * 256;
            int r = idx >> 3, u = idx & 7;
            cp_async16(as + SWZ128((uint32_t)(r * 128 + u * 16)),
                       Ap + (size_t)r * Kext + u * 8);
        }
#pragma unroll
        for (int i = 0; i < BN / 32; i++) {
            int idx = tid + i * 256;
            int r = idx >> 3, u = idx & 7;
            cp_async16(bs + SWZ128((uint32_t)(r * 128 + u * 16)),
                       Bp + (size_t)r * Kext + u * 8);
        }
    };

    load_stage(0, 0); CP_COMMIT();
    if (nc > 1) load_stage(1, 1);
    CP_COMMIT();

    for (int c = 0; c < nc; c++) {
        if (c == nc - 1) { CP_WAIT0(); } else { CP_WAIT1(); }
        __syncthreads();
        if (c + 2 < nc) {
            load_stage(c + 2, (c + 2) % 3);
            CP_COMMIT();
        }
        uint32_t as = smb + (c % 3) * STAGE;
        uint32_t bs = as + 128 * 128;
#pragma unroll
        for (int ks = 0; ks < 4; ks++) {
            uint32_t a[2][4], b[NT][2];
#pragma unroll
            for (int mt = 0; mt < 2; mt++) {
                int row = wm * 32 + mt * 16 + (lane & 15);
                int kb = ks * 32 + ((lane >> 4) << 4);
                uint32_t addr = as + SWZ128((uint32_t)(row * 128 + kb));
                ldmatrix_x4(addr, a[mt][0], a[mt][1], a[mt][2], a[mt][3]);
            }
#pragma unroll
            for (int p = 0; p < NT / 2; p++) {
                int row = wn * WNW + p * 16 + ((lane >> 4) << 3) + (lane & 7);
                int kb = ks * 32 + ((((lane & 15) >> 3)) << 4);
                uint32_t addr = bs + SWZ128((uint32_t)(row * 128 + kb));
                ldmatrix_x4(addr, b[2 * p][0], b[2 * p][1], b[2 * p + 1][0],
                            b[2 * p + 1][1]);
            }
#pragma unroll
            for (int mt = 0; mt < 2; mt++)
#pragma unroll
                for (int nt = 0; nt < NT; nt++)
                    mma16816(acc[mt][nt], a[mt], b[nt]);
        }
        __syncthreads();
    }

    // ---- epilogue ----
    const int EPR = (OUTM == 1) ? (Ntot / CK) : 1;
#pragma unroll
    for (int mt = 0; mt < 2; mt++) {
#pragma unroll
        for (int nt = 0; nt < NT; nt++) {
            int col = col0 + wn * WNW + nt * 8 + 2 * (lane & 3);
            float bia0 = bias[col], bia1 = bias[col + 1];
#pragma unroll
            for (int half = 0; half < 2; half++) {
                int row = row0 + wm * 32 + mt * 16 + (lane >> 2) + half * 8;
                float v0 = acc[mt][nt][half * 2 + 0] + bia0;
                float v1 = acc[mt][nt][half * 2 + 1] + bia1;
                if (EPI == 1) {
                    v0 = (v0 > 0.f) ? (v0 + 1.f) : expf(v0);
                    v1 = (v1 > 0.f) ? (v1 + 1.f) : expf(v1);
                } else if (EPI == 2) {
                    v0 = 0.5f * v0 * (1.f + erff(v0 * 0.70710678118654752f));
                    v1 = 0.5f * v1 * (1.f + erff(v1 * 0.70710678118654752f));
                }
                if (OUTM == 0) {
                    float2 o = make_float2(v0, v1);
                    *(float2*)&Cf[(size_t)row * Ntot + col] = o;
                } else {
                    bf16 h0 = __float2bfloat16(v0);
                    bf16 h1 = __float2bfloat16(v1);
                    bf16 l0 = __float2bfloat16(v0 - __bfloat162float(h0));
                    bf16 l1 = __float2bfloat16(v1 - __bfloat162float(h1));
                    int rp = row * EPR + col / CK;
                    int cp = col % CK;
                    size_t base = (size_t)rp * 3 * CK + cp;
                    bf162 ph; ph.x = h0; ph.y = h1;
                    bf162 pl; pl.x = l0; pl.y = l1;
                    *(bf162*)&Cext[base] = ph;
                    *(bf162*)&Cext[base + CK] = pl;
                    *(bf162*)&Cext[base + 2 * CK] = ph;
                }
            }
        }
    }
}

// ===================== zero =====================
__global__ void zero_kernel(float* __restrict__ kv, float* __restrict__ ksum) {
    int i = blockIdx.x * blockDim.x + threadIdx.x;
    if (i < BB * HH * DD * DD) kv[i] = 0.f;
    if (i < BB * HH * DD) ksum[i] = 0.f;
}

// ===================== kv context =====================
__global__ void kv_kernel(const float* __restrict__ ka, const float* __restrict__ v,
                          float* __restrict__ kv) {
    const int bh = blockIdx.x;
    const int b = bh / HH, h = bh % HH;
    const int m0 = blockIdx.y * 256;
    __shared__ float ka_s[16][64];
    __shared__ float v_s[16][64];
    const int tid = threadIdx.x;
    const int tx = tid % 16, ty = tid / 16;
    float acc[4][4];
#pragma unroll
    for (int i = 0; i < 4; i++)
#pragma unroll
        for (int j = 0; j < 4; j++) acc[i][j] = 0.f;
    const size_t base = (size_t)b * MMCTX * EE + (size_t)h * DD;
    for (int mt = 0; mt < 16; mt++) {
        const int m = m0 + mt * 16;
        {
            int mm = tid / 16, e4 = tid % 16;
            size_t g = base + (size_t)(m + mm) * EE + e4 * 4;
            *(float4*)&ka_s[mm][e4 * 4] = *(const float4*)&ka[g];
            *(float4*)&v_s[mm][e4 * 4] = *(const float4*)&v[g];
        }
        __syncthreads();
#pragma unroll
        for (int mm = 0; mm < 16; mm++) {
            float rd[4];
            float4 re = *(const float4*)&v_s[mm][tx * 4];
#pragma unroll
            for (int i = 0; i < 4; i++) rd[i] = ka_s[mm][ty * 4 + i];
#pragma unroll
            for (int i = 0; i < 4; i++) {
                acc[i][0] += rd[i] * re.x; acc[i][1] += rd[i] * re.y;
                acc[i][2] += rd[i] * re.z; acc[i][3] += rd[i] * re.w;
            }
        }
        __syncthreads();
    }
    const float inv_m = 1.f / (float)MMCTX;
#pragma unroll
    for (int i = 0; i < 4; i++)
#pragma unroll
        for (int j = 0; j < 4; j++)
            atomicAdd(&kv[((size_t)bh * DD + ty * 4 + i) * DD + tx * 4 + j],
                      acc[i][j] * inv_m);
}

// ===================== k_sum =====================
__global__ void ksum_kernel(const float* __restrict__ ka, float* __restrict__ ksum) {
    const int bh = blockIdx.x;
    const int b = bh / HH, h = bh % HH;
    const int m0 = blockIdx.y * 512;
    const int d = threadIdx.x;
    float s = 0.f;
    const size_t base = (size_t)b * MMCTX * EE + (size_t)h * DD + d;
    for (int m = 0; m < 512; m++) s += ka[base + (size_t)(m0 + m) * EE];
    atomicAdd(&ksum[bh * DD + d], s * (1.f / (float)MMCTX));
}

// ===================== out einsum + normalize -> attn ext =====================
#define OUT_ROWS 32
__global__ void out_kernel(const float* __restrict__ q, const float* __restrict__ kv,
                           const float* __restrict__ ksum,
                           bf16* __restrict__ attn_ext) {
    extern __shared__ float smf[];
    float* kv_s = smf;
    float* ks_s = smf + HH * DD * DD;
    const int b = blockIdx.x;
    const int r0 = blockIdx.y * OUT_ROWS;
    const int tid = threadIdx.x;
    for (int i = tid; i < HH * DD * DD / 4; i += 256)
        *(float4*)&kv_s[i * 4] = *(const float4*)&kv[(size_t)b * HH * DD * DD + i * 4];
    for (int i = tid; i < HH * DD / 4; i += 256)
        *(float4*)&ks_s[i * 4] = *(const float4*)&ksum[b * HH * DD + i * 4];
    __syncthreads();
    const int h = tid / 32, lane = tid % 32;
    const float* kvh = &kv_s[h * DD * DD];
    for (int r = 0; r < OUT_ROWS; r++) {
        const int n = r0 + r;
        const size_t row = (size_t)b * NN + n;
        const size_t qb = row * EE + h * DD;
        float q0 = q[qb + lane];
        float q1 = q[qb + lane + 32];
        float dp = q0 * ks_s[h * DD + lane] + q1 * ks_s[h * DD + lane + 32];
#pragma unroll
        for (int off = 16; off; off >>= 1) dp += __shfl_xor_sync(0xffffffffu, dp, off);
        dp = fmaxf(dp, 1e-6f);
        float a0 = 0.f, a1 = 0.f;
#pragma unroll
        for (int d = 0; d < DD; d++) {
            float qd = __shfl_sync(0xffffffffu, (d < 32) ? q0 : q1, d & 31);
            float2 kvv = *(const float2*)&kvh[d * DD + lane * 2];
            a0 += qd * kvv.x;
            a1 += qd * kvv.y;
        }
        a0 /= dp; a1 /= dp;
        a0 = isnan(a0) ? 0.f : fminf(fmaxf(a0, -65000.f), 65000.f);
        a1 = isnan(a1) ? 0.f : fminf(fmaxf(a1, -65000.f), 65000.f);
        bf16 h0 = __float2bfloat16(a0), h1 = __float2bfloat16(a1);
        bf16 l0 = __float2bfloat16(a0 - __bfloat162float(h0));
        bf16 l1 = __float2bfloat16(a1 - __bfloat162float(h1));
        bf162 ph; ph.x = h0; ph.y = h1;
        bf162 pl; pl.x = l0; pl.y = l1;
        size_t base = row * (3 * EE) + h * DD + lane * 2;
        *(bf162*)&attn_ext[base] = ph;
        *(bf162*)&attn_ext[base + EE] = pl;
        *(bf162*)&attn_ext[base + 2 * EE] = ph;
    }
}

// ===================== launch =====================
extern "C" void kernel_launch(void* const* d_in, const int* in_sizes, int n_in,
                              void* d_out, int out_size) {
    const float* query = (const float*)d_in[0];
    const float* key   = (const float*)d_in[1];
    const float* value = (const float*)d_in[2];
    const float* Wq = (const float*)d_in[3];
    const float* bq = (const float*)d_in[4];
    const float* Wk = (const float*)d_in[5];
    const float* bk = (const float*)d_in[6];
    const float* Wv = (const float*)d_in[7];
    const float* bv = (const float*)d_in[8];
    const float* W1 = (const float*)d_in[9];
    const float* b1 = (const float*)d_in[10];
    const float* W2 = (const float*)d_in[11];
    const float* b2 = (const float*)d_in[12];
    const float* Wo = (const float*)d_in[13];
    const float* bo = (const float*)d_in[14];
    float* out = (float*)d_out;

    float *q_s, *v_s, *ka_s, *kv_s, *ksum_s;
    cudaGetSymbolAddress((void**)&q_s, g_q);
    cudaGetSymbolAddress((void**)&v_s, g_v);
    cudaGetSymbolAddress((void**)&ka_s, g_ka);
    cudaGetSymbolAddress((void**)&kv_s, g_kv);
    cudaGetSymbolAddress((void**)&ksum_s, g_ksum);

    bf16 *qin, *kin, *vin, *kact, *h1e, *attn;
    bf16 *Wqe, *Wke, *Wve, *Woe, *W1e, *W2e;
    cudaGetSymbolAddress((void**)&qin, g_qin_ext);
    cudaGetSymbolAddress((void**)&kin, g_kin_ext);
    cudaGetSymbolAddress((void**)&vin, g_vin_ext);
    cudaGetSymbolAddress((void**)&kact, g_kact_ext);
    cudaGetSymbolAddress((void**)&h1e, g_h1_ext);
    cudaGetSymbolAddress((void**)&attn, g_attn_ext);
    cudaGetSymbolAddress((void**)&Wqe, g_Wq_ext);
    cudaGetSymbolAddress((void**)&Wke, g_Wk_ext);
    cudaGetSymbolAddress((void**)&Wve, g_Wv_ext);
    cudaGetSymbolAddress((void**)&Woe, g_Wo_ext);
    cudaGetSymbolAddress((void**)&W1e, g_W1_ext);
    cudaGetSymbolAddress((void**)&W2e, g_W2_ext);

    const int SM128 = 3 * (256 * 128);  // 98304
    const int SM64  = 3 * (192 * 128);  // 73728
    cudaFuncSetAttribute((const void*)mma_gemm<128, 1, 0>,
                         cudaFuncAttributeMaxDynamicSharedMemorySize, SM128);
    cudaFuncSetAttribute((const void*)mma_gemm<128, 1, 1>,
                         cudaFuncAttributeMaxDynamicSharedMemorySize, SM128);
    cudaFuncSetAttribute((const void*)mma_gemm<128, 0, 0>,
                         cudaFuncAttributeMaxDynamicSharedMemorySize, SM128);
    cudaFuncSetAttribute((const void*)mma_gemm<128, 2, 1>,
                         cudaFuncAttributeMaxDynamicSharedMemorySize, SM128);
    cudaFuncSetAttribute((const void*)mma_gemm<64, 1, 0>,
                         cudaFuncAttributeMaxDynamicSharedMemorySize, SM64);

    // ---- conversions
    {
        int nEl = ROWS_QK * EE;
        int blocks = (nEl + 255) / 256;
        conv_act_ext<<<blocks, 256>>>(query, qin, nEl, EE);
        conv_act_ext<<<blocks, 256>>>(key, kin, nEl, EE);
        conv_act_ext<<<blocks, 256>>>(value, vin, nEl, EE);
        conv_wt_ext<<<(EE * EE + 255) / 256, 256>>>(Wq, Wqe, EE, EE);
        conv_wt_ext<<<(EE * EE + 255) / 256, 256>>>(Wk, Wke, EE, EE);
        conv_wt_ext<<<(EE * EE + 255) / 256, 256>>>(Wv, Wve, EE, EE);
        conv_wt_ext<<<(EE * EE + 255) / 256, 256>>>(Wo, Woe, EE, EE);
        conv_wt_ext<<<(64 * 128 + 255) / 256, 256>>>(W1, W1e, 64, 128);
        conv_wt_ext<<<(128 * 64 + 255) / 256, 256>>>(W2, W2e, 128, 64);
    }

    // ---- projections
    {
        dim3 grid(EE / 128, ROWS_QK / 128);
        mma_gemm<128, 1, 0><<<grid, 256, SM128>>>(qin, Wqe, bq, q_s, nullptr,
                                                  EE, 3 * EE, 0);
        mma_gemm<128, 1, 1><<<grid, 256, SM128>>>(kin, Wke, bk, nullptr, kact,
                                                  EE, 3 * EE, 64);
        mma_gemm<128, 0, 0><<<grid, 256, SM128>>>(vin, Wve, bv, v_s, nullptr,
                                                  EE, 3 * EE, 0);
    }
    // ---- key MLP
    {
        dim3 grid1(1, ROWS_MLP / 128);
        mma_gemm<128, 2, 1><<<grid1, 256, SM128>>>(kact, W1e, b1, nullptr, h1e,
                                                   128, 3 * 64, 128);
        mma_gemm<64, 1, 0><<<grid1, 256, SM64>>>(h1e, W2e, b2, ka_s, nullptr,
                                                 64, 3 * 128, 0);
    }
    // ---- kv context + ksum
    {
        int nz = BB * HH * DD * DD;
        zero_kernel<<<(nz + 255) / 256, 256>>>(kv_s, ksum_s);
        dim3 gkv(BB * HH, MMCTX / 256);
        kv_kernel<<<gkv, 256>>>(ka_s, v_s, kv_s);
        dim3 gks(BB * HH, MMCTX / 512);
        ksum_kernel<<<gks, 64>>>(ka_s, ksum_s);
    }
    // ---- out einsum + normalize -> attn ext
    {
        size_t smem = (size_t)(HH * DD * DD + HH * DD) * sizeof(float);
        cudaFuncSetAttribute(out_kernel, cudaFuncAttributeMaxDynamicSharedMemorySize,
                             (int)smem);
        dim3 go(BB, NN / OUT_ROWS);
        out_kernel<<<go, 256, smem>>>(q_s, kv_s, ksum_s, attn);
    }
    // ---- final projection
    {
        dim3 grid(EE / 128, ROWS_QK / 128);
        mma_gemm<128, 0, 0><<<grid, 256, SM128>>>(attn, Woe, bo, out, nullptr,
                                                  EE, 3 * EE, 0);
    }
}

// round 5
// speedup vs baseline: 2.0519x; 1.1312x over previous
#include <cuda_runtime.h>
#include <cuda_bf16.h>
#include <math.h>
#include <stdint.h>

#define BB 4
#define NN 4096
#define MMCTX 4096
#define EE 512
#define HH 8
#define DD 64
#define ROWS_QK (BB * NN)          // 16384
#define ROWS_MLP (BB * MMCTX * HH) // 131072

typedef __nv_bfloat16 bf16;
typedef __nv_bfloat162 bf162;

__device__ __forceinline__ uint32_t smem_u32(const void* p) {
    uint32_t a;
    asm("{ .reg .u64 t; cvta.to.shared.u64 t, %1; cvt.u32.u64 %0, t; }"
        : "=r"(a) : "l"(p));
    return a;
}

#define SWZ128(b) ((b) ^ (((b) >> 3) & 0x70))

__device__ __forceinline__ void cp_async16(uint32_t dst, const void* src) {
    asm volatile("cp.async.cg.shared.global [%0], [%1], 16;\n"
                 :: "r"(dst), "l"(src));
}
#define CP_COMMIT() asm volatile("cp.async.commit_group;\n" ::: "memory")
#define CP_WAIT1() asm volatile("cp.async.wait_group 1;\n" ::: "memory")
#define CP_WAIT0() asm volatile("cp.async.wait_group 0;\n" ::: "memory")

__device__ __forceinline__ void ldmatrix_x4(uint32_t addr, uint32_t& r0,
                                            uint32_t& r1, uint32_t& r2,
                                            uint32_t& r3) {
    asm volatile("ldmatrix.sync.aligned.m8n8.x4.shared.b16 {%0,%1,%2,%3}, [%4];"
                 : "=r"(r0), "=r"(r1), "=r"(r2), "=r"(r3) : "r"(addr));
}

__device__ __forceinline__ void mma16816(float* c, const uint32_t* a,
                                         const uint32_t* b) {
    asm volatile(
        "mma.sync.aligned.m16n8k16.row.col.f32.bf16.bf16.f32 "
        "{%0,%1,%2,%3}, {%4,%5,%6,%7}, {%8,%9}, {%0,%1,%2,%3};"
        : "+f"(c[0]), "+f"(c[1]), "+f"(c[2]), "+f"(c[3])
        : "r"(a[0]), "r"(a[1]), "r"(a[2]), "r"(a[3]), "r"(b[0]), "r"(b[1]));
}

// ===================== scratch =====================
__device__ float g_q[ROWS_QK * EE];
__device__ float g_v[ROWS_QK * EE];
__device__ float g_ka[ROWS_MLP * DD];
__device__ float g_kv[BB * HH * DD * DD];
__device__ float g_ksum[BB * HH * DD];

__device__ bf16 g_qin_h[ROWS_QK * EE], g_qin_l[ROWS_QK * EE];
__device__ bf16 g_kin_h[ROWS_QK * EE], g_kin_l[ROWS_QK * EE];
__device__ bf16 g_vin_h[ROWS_QK * EE], g_vin_l[ROWS_QK * EE];
__device__ bf16 g_kact_h[ROWS_MLP * DD], g_kact_l[ROWS_MLP * DD];
__device__ bf16 g_h1_h[ROWS_MLP * 128], g_h1_l[ROWS_MLP * 128];
__device__ bf16 g_attn_h[ROWS_QK * EE], g_attn_l[ROWS_QK * EE];

__device__ bf16 g_Wq_h[EE * EE], g_Wq_l[EE * EE];
__device__ bf16 g_Wk_h[EE * EE], g_Wk_l[EE * EE];
__device__ bf16 g_Wv_h[EE * EE], g_Wv_l[EE * EE];
__device__ bf16 g_Wo_h[EE * EE], g_Wo_l[EE * EE];
__device__ bf16 g_W1_h[128 * 64], g_W1_l[128 * 64];
__device__ bf16 g_W2_h[64 * 128], g_W2_l[64 * 128];

// ===================== conversions =====================
__global__ void conv_act(const float* __restrict__ x, bf16* __restrict__ hi,
                         bf16* __restrict__ lo, int n) {
    int i = (blockIdx.x * blockDim.x + threadIdx.x) * 4;
    if (i >= n) return;
    float4 v = *(const float4*)&x[i];
    bf16 h0 = __float2bfloat16(v.x), h1 = __float2bfloat16(v.y);
    bf16 h2 = __float2bfloat16(v.z), h3 = __float2bfloat16(v.w);
    bf16 l0 = __float2bfloat16(v.x - __bfloat162float(h0));
    bf16 l1 = __float2bfloat16(v.y - __bfloat162float(h1));
    bf16 l2 = __float2bfloat16(v.z - __bfloat162float(h2));
    bf16 l3 = __float2bfloat16(v.w - __bfloat162float(h3));
    bf162 a; a.x = h0; a.y = h1;
    bf162 b; b.x = h2; b.y = h3;
    bf162 c; c.x = l0; c.y = l1;
    bf162 d; d.x = l2; d.y = l3;
    *(bf162*)&hi[i] = a; *(bf162*)&hi[i + 2] = b;
    *(bf162*)&lo[i] = c; *(bf162*)&lo[i + 2] = d;
}

// W[k*N+n] -> Bh/Bl[n*K+k]
__global__ void conv_wt(const float* __restrict__ W, bf16* __restrict__ hi,
                        bf16* __restrict__ lo, int K, int N) {
    int idx = blockIdx.x * blockDim.x + threadIdx.x;
    if (idx >= K * N) return;
    int k = idx / N, n = idx % N;
    float v = W[idx];
    bf16 h = __float2bfloat16(v);
    hi[n * K + k] = h;
    lo[n * K + k] = __float2bfloat16(v - __bfloat162float(h));
}

// ===================== HMMA split GEMM =====================
// C[M,N] = epi(A @ W^T + bias): A hi/lo [M,K] row-major, B hi/lo [N,K] row-major.
// 3-product: Ah*Bh + Al*Bh + Ah*Bl. EPI: 0 none, 1 elu+1, 2 gelu.
// OUTM: 0 -> Cf fp32 [M,Ntot]; 1 -> Chi/Clo with row remap chunk CK.
template <int BN, int EPI, int OUTM>
__global__ void __launch_bounds__(256, 2)
mma_gemm3(const bf16* __restrict__ Ah, const bf16* __restrict__ Al,
          const bf16* __restrict__ Bh, const bf16* __restrict__ Bl,
          const float* __restrict__ bias, float* __restrict__ Cf,
          bf16* __restrict__ Chi, bf16* __restrict__ Clo, int Ntot, int K,
          int CK) {
    extern __shared__ char sm[];
    // per stage: A 128 rows x 128B ([hi 64B | lo 64B]), B BN rows x 128B
    constexpr int STAGE = (128 + BN) * 128;
    constexpr int NT = (BN == 128) ? 8 : 4;
    constexpr int WNW = NT * 8;

    const int tid = threadIdx.x;
    const int lane = tid & 31, wid = tid >> 5;
    const int wm = wid >> 1, wn = wid & 1;
    const int row0 = blockIdx.y * 128;
    const int col0 = blockIdx.x * BN;
    const uint32_t smb = smem_u32(sm);
    const int nc = K / 32;

    float acc[2][NT][4];
#pragma unroll
    for (int i = 0; i < 2; i++)
#pragma unroll
        for (int j = 0; j < NT; j++)
#pragma unroll
            for (int t = 0; t < 4; t++) acc[i][j][t] = 0.f;

    auto load_stage = [&](int c, int buf) {
        uint32_t as = smb + buf * STAGE;
        uint32_t bs = as + 128 * 128;
        const bf16* Aph = Ah + (size_t)row0 * K + c * 32;
        const bf16* Apl = Al + (size_t)row0 * K + c * 32;
        const bf16* Bph = Bh + (size_t)col0 * K + c * 32;
        const bf16* Bpl = Bl + (size_t)col0 * K + c * 32;
        // A: 128 rows x 4 segs of 16B, hi then lo
#pragma unroll
        for (int i = 0; i < 2; i++) {
            int idx = tid + i * 256;
            int r = idx >> 2, u = idx & 3;
            cp_async16(as + SWZ128((uint32_t)(r * 128 + u * 16)),
                       Aph + (size_t)r * K + u * 8);
            cp_async16(as + SWZ128((uint32_t)(r * 128 + 64 + u * 16)),
                       Apl + (size_t)r * K + u * 8);
        }
#pragma unroll
        for (int i = 0; i < BN / 64; i++) {
            int idx = tid + i * 256;
            int r = idx >> 2, u = idx & 3;
            cp_async16(bs + SWZ128((uint32_t)(r * 128 + u * 16)),
                       Bph + (size_t)r * K + u * 8);
            cp_async16(bs + SWZ128((uint32_t)(r * 128 + 64 + u * 16)),
                       Bpl + (size_t)r * K + u * 8);
        }
    };

    load_stage(0, 0); CP_COMMIT();
    if (nc > 1) load_stage(1, 1);
    CP_COMMIT();

    for (int c = 0; c < nc; c++) {
        if (c == nc - 1) { CP_WAIT0(); } else { CP_WAIT1(); }
        __syncthreads();
        if (c + 2 < nc) {
            load_stage(c + 2, (c + 2) % 3);
            CP_COMMIT();
        }
        uint32_t as = smb + (c % 3) * STAGE;
        uint32_t bs = as + 128 * 128;
#pragma unroll
        for (int ks = 0; ks < 2; ks++) {
            uint32_t ah[2][4], al[2][4], bb[NT][2];
            // A fragments (hi and lo)
#pragma unroll
            for (int mt = 0; mt < 2; mt++) {
                int row = wm * 32 + mt * 16 + (lane & 15);
                int kb = ks * 32 + ((lane >> 4) << 4);
                ldmatrix_x4(as + SWZ128((uint32_t)(row * 128 + kb)),
                            ah[mt][0], ah[mt][1], ah[mt][2], ah[mt][3]);
                ldmatrix_x4(as + SWZ128((uint32_t)(row * 128 + 64 + kb)),
                            al[mt][0], al[mt][1], al[mt][2], al[mt][3]);
            }
            // B hi fragments
#pragma unroll
            for (int p = 0; p < NT / 2; p++) {
                int row = wn * WNW + p * 16 + ((lane >> 4) << 3) + (lane & 7);
                int kb = ks * 32 + (((lane & 15) >> 3) << 4);
                ldmatrix_x4(bs + SWZ128((uint32_t)(row * 128 + kb)),
                            bb[2 * p][0], bb[2 * p][1], bb[2 * p + 1][0],
                            bb[2 * p + 1][1]);
            }
#pragma unroll
            for (int mt = 0; mt < 2; mt++)
#pragma unroll
                for (int nt = 0; nt < NT; nt++) {
                    mma16816(acc[mt][nt], ah[mt], bb[nt]);
                }
#pragma unroll
            for (int mt = 0; mt < 2; mt++)
#pragma unroll
                for (int nt = 0; nt < NT; nt++) {
                    mma16816(acc[mt][nt], al[mt], bb[nt]);
                }
            // B lo fragments (reuse bb regs)
#pragma unroll
            for (int p = 0; p < NT / 2; p++) {
                int row = wn * WNW + p * 16 + ((lane >> 4) << 3) + (lane & 7);
                int kb = ks * 32 + (((lane & 15) >> 3) << 4);
                ldmatrix_x4(bs + SWZ128((uint32_t)(row * 128 + 64 + kb)),
                            bb[2 * p][0], bb[2 * p][1], bb[2 * p + 1][0],
                            bb[2 * p + 1][1]);
            }
#pragma unroll
            for (int mt = 0; mt < 2; mt++)
#pragma unroll
                for (int nt = 0; nt < NT; nt++) {
                    mma16816(acc[mt][nt], ah[mt], bb[nt]);
                }
        }
        __syncthreads();
    }

    // ---- epilogue ----
    const int EPR = (OUTM == 1) ? (Ntot / CK) : 1;
#pragma unroll
    for (int mt = 0; mt < 2; mt++) {
#pragma unroll
        for (int nt = 0; nt < NT; nt++) {
            int col = col0 + wn * WNW + nt * 8 + 2 * (lane & 3);
            float bia0 = bias[col], bia1 = bias[col + 1];
#pragma unroll
            for (int half = 0; half < 2; half++) {
                int row = row0 + wm * 32 + mt * 16 + (lane >> 2) + half * 8;
                float v0 = acc[mt][nt][half * 2 + 0] + bia0;
                float v1 = acc[mt][nt][half * 2 + 1] + bia1;
                if (EPI == 1) {
                    v0 = (v0 > 0.f) ? (v0 + 1.f) : expf(v0);
                    v1 = (v1 > 0.f) ? (v1 + 1.f) : expf(v1);
                } else if (EPI == 2) {
                    v0 = 0.5f * v0 * (1.f + erff(v0 * 0.70710678118654752f));
                    v1 = 0.5f * v1 * (1.f + erff(v1 * 0.70710678118654752f));
                }
                if (OUTM == 0) {
                    float2 o = make_float2(v0, v1);
                    *(float2*)&Cf[(size_t)row * Ntot + col] = o;
                } else {
                    bf16 h0 = __float2bfloat16(v0);
                    bf16 h1 = __float2bfloat16(v1);
                    bf16 l0 = __float2bfloat16(v0 - __bfloat162float(h0));
                    bf16 l1 = __float2bfloat16(v1 - __bfloat162float(h1));
                    int rp = row * EPR + col / CK;
                    int cp = col % CK;
                    size_t base = (size_t)rp * CK + cp;
                    bf162 ph; ph.x = h0; ph.y = h1;
                    bf162 pl; pl.x = l0; pl.y = l1;
                    *(bf162*)&Chi[base] = ph;
                    *(bf162*)&Clo[base] = pl;
                }
            }
        }
    }
}

// ===================== zero =====================
__global__ void zero_kernel(float* __restrict__ kv, float* __restrict__ ksum) {
    int i = blockIdx.x * blockDim.x + threadIdx.x;
    if (i < BB * HH * DD * DD) kv[i] = 0.f;
    if (i < BB * HH * DD) ksum[i] = 0.f;
}

// ===================== kv context =====================
__global__ void kv_kernel(const float* __restrict__ ka, const float* __restrict__ v,
                          float* __restrict__ kv) {
    const int bh = blockIdx.x;
    const int b = bh / HH, h = bh % HH;
    const int m0 = blockIdx.y * 256;
    __shared__ float ka_s[16][64];
    __shared__ float v_s[16][64];
    const int tid = threadIdx.x;
    const int tx = tid % 16, ty = tid / 16;
    float acc[4][4];
#pragma unroll
    for (int i = 0; i < 4; i++)
#pragma unroll
        for (int j = 0; j < 4; j++) acc[i][j] = 0.f;
    const size_t base = (size_t)b * MMCTX * EE + (size_t)h * DD;
    for (int mt = 0; mt < 16; mt++) {
        const int m = m0 + mt * 16;
        {
            int mm = tid / 16, e4 = tid % 16;
            size_t g = base + (size_t)(m + mm) * EE + e4 * 4;
            *(float4*)&ka_s[mm][e4 * 4] = *(const float4*)&ka[g];
            *(float4*)&v_s[mm][e4 * 4] = *(const float4*)&v[g];
        }
        __syncthreads();
#pragma unroll
        for (int mm = 0; mm < 16; mm++) {
            float rd[4];
            float4 re = *(const float4*)&v_s[mm][tx * 4];
#pragma unroll
            for (int i = 0; i < 4; i++) rd[i] = ka_s[mm][ty * 4 + i];
#pragma unroll
            for (int i = 0; i < 4; i++) {
                acc[i][0] += rd[i] * re.x; acc[i][1] += rd[i] * re.y;
                acc[i][2] += rd[i] * re.z; acc[i][3] += rd[i] * re.w;
            }
        }
        __syncthreads();
    }
    const float inv_m = 1.f / (float)MMCTX;
#pragma unroll
    for (int i = 0; i < 4; i++)
#pragma unroll
        for (int j = 0; j < 4; j++)
            atomicAdd(&kv[((size_t)bh * DD + ty * 4 + i) * DD + tx * 4 + j],
                      acc[i][j] * inv_m);
}

// ===================== k_sum =====================
__global__ void ksum_kernel(const float* __restrict__ ka, float* __restrict__ ksum) {
    const int bh = blockIdx.x;
    const int b = bh / HH, h = bh % HH;
    const int m0 = blockIdx.y * 512;
    const int d = threadIdx.x;
    float s = 0.f;
    const size_t base = (size_t)b * MMCTX * EE + (size_t)h * DD + d;
    for (int m = 0; m < 512; m++) s += ka[base + (size_t)(m0 + m) * EE];
    atomicAdd(&ksum[bh * DD + d], s * (1.f / (float)MMCTX));
}

// ===================== out einsum + normalize -> attn hi/lo =====================
#define OUT_ROWS 32
__global__ void out_kernel(const float* __restrict__ q, const float* __restrict__ kv,
                           const float* __restrict__ ksum,
                           bf16* __restrict__ attn_h, bf16* __restrict__ attn_l) {
    extern __shared__ float smf[];
    float* kv_s = smf;
    float* ks_s = smf + HH * DD * DD;
    const int b = blockIdx.x;
    const int r0 = blockIdx.y * OUT_ROWS;
    const int tid = threadIdx.x;
    for (int i = tid; i < HH * DD * DD / 4; i += 256)
        *(float4*)&kv_s[i * 4] = *(const float4*)&kv[(size_t)b * HH * DD * DD + i * 4];
    for (int i = tid; i < HH * DD / 4; i += 256)
        *(float4*)&ks_s[i * 4] = *(const float4*)&ksum[b * HH * DD + i * 4];
    __syncthreads();
    const int h = tid / 32, lane = tid % 32;
    const float* kvh = &kv_s[h * DD * DD];
    for (int r = 0; r < OUT_ROWS; r++) {
        const int n = r0 + r;
        const size_t row = (size_t)b * NN + n;
        const size_t qb = row * EE + h * DD;
        float q0 = q[qb + lane];
        float q1 = q[qb + lane + 32];
        float dp = q0 * ks_s[h * DD + lane] + q1 * ks_s[h * DD + lane + 32];
#pragma unroll
        for (int off = 16; off; off >>= 1) dp += __shfl_xor_sync(0xffffffffu, dp, off);
        dp = fmaxf(dp, 1e-6f);
        float a0 = 0.f, a1 = 0.f;
#pragma unroll
        for (int d = 0; d < DD; d++) {
            float qd = __shfl_sync(0xffffffffu, (d < 32) ? q0 : q1, d & 31);
            float2 kvv = *(const float2*)&kvh[d * DD + lane * 2];
            a0 += qd * kvv.x;
            a1 += qd * kvv.y;
        }
        a0 /= dp; a1 /= dp;
        a0 = isnan(a0) ? 0.f : fminf(fmaxf(a0, -65000.f), 65000.f);
        a1 = isnan(a1) ? 0.f : fminf(fmaxf(a1, -65000.f), 65000.f);
        bf16 h0 = __float2bfloat16(a0), h1 = __float2bfloat16(a1);
        bf16 l0 = __float2bfloat16(a0 - __bfloat162float(h0));
        bf16 l1 = __float2bfloat16(a1 - __bfloat162float(h1));
        bf162 ph; ph.x = h0; ph.y = h1;
        bf162 pl; pl.x = l0; pl.y = l1;
        *(bf162*)&attn_h[qb + lane * 2] = ph;
        *(bf162*)&attn_l[qb + lane * 2] = pl;
    }
}

// ===================== launch =====================
extern "C" void kernel_launch(void* const* d_in, const int* in_sizes, int n_in,
                              void* d_out, int out_size) {
    const float* query = (const float*)d_in[0];
    const float* key   = (const float*)d_in[1];
    const float* value = (const float*)d_in[2];
    const float* Wq = (const float*)d_in[3];
    const float* bq = (const float*)d_in[4];
    const float* Wk = (const float*)d_in[5];
    const float* bk = (const float*)d_in[6];
    const float* Wv = (const float*)d_in[7];
    const float* bv = (const float*)d_in[8];
    const float* W1 = (const float*)d_in[9];
    const float* b1 = (const float*)d_in[10];
    const float* W2 = (const float*)d_in[11];
    const float* b2 = (const float*)d_in[12];
    const float* Wo = (const float*)d_in[13];
    const float* bo = (const float*)d_in[14];
    float* out = (float*)d_out;

    float *q_s, *v_s, *ka_s, *kv_s, *ksum_s;
    cudaGetSymbolAddress((void**)&q_s, g_q);
    cudaGetSymbolAddress((void**)&v_s, g_v);
    cudaGetSymbolAddress((void**)&ka_s, g_ka);
    cudaGetSymbolAddress((void**)&kv_s, g_kv);
    cudaGetSymbolAddress((void**)&ksum_s, g_ksum);

    bf16 *qin_h, *qin_l, *kin_h, *kin_l, *vin_h, *vin_l;
    bf16 *kact_h, *kact_l, *h1_h, *h1_l, *attn_h, *attn_l;
    bf16 *Wq_h, *Wq_l, *Wk_h, *Wk_l, *Wv_h, *Wv_l, *Wo_h, *Wo_l;
    bf16 *W1_h, *W1_l, *W2_h, *W2_l;
    cudaGetSymbolAddress((void**)&qin_h, g_qin_h);
    cudaGetSymbolAddress((void**)&qin_l, g_qin_l);
    cudaGetSymbolAddress((void**)&kin_h, g_kin_h);
    cudaGetSymbolAddress((void**)&kin_l, g_kin_l);
    cudaGetSymbolAddress((void**)&vin_h, g_vin_h);
    cudaGetSymbolAddress((void**)&vin_l, g_vin_l);
    cudaGetSymbolAddress((void**)&kact_h, g_kact_h);
    cudaGetSymbolAddress((void**)&kact_l, g_kact_l);
    cudaGetSymbolAddress((void**)&h1_h, g_h1_h);
    cudaGetSymbolAddress((void**)&h1_l, g_h1_l);
    cudaGetSymbolAddress((void**)&attn_h, g_attn_h);
    cudaGetSymbolAddress((void**)&attn_l, g_attn_l);
    cudaGetSymbolAddress((void**)&Wq_h, g_Wq_h);
    cudaGetSymbolAddress((void**)&Wq_l, g_Wq_l);
    cudaGetSymbolAddress((void**)&Wk_h, g_Wk_h);
    cudaGetSymbolAddress((void**)&Wk_l, g_Wk_l);
    cudaGetSymbolAddress((void**)&Wv_h, g_Wv_h);
    cudaGetSymbolAddress((void**)&Wv_l, g_Wv_l);
    cudaGetSymbolAddress((void**)&Wo_h, g_Wo_h);
    cudaGetSymbolAddress((void**)&Wo_l, g_Wo_l);
    cudaGetSymbolAddress((void**)&W1_h, g_W1_h);
    cudaGetSymbolAddress((void**)&W1_l, g_W1_l);
    cudaGetSymbolAddress((void**)&W2_h, g_W2_h);
    cudaGetSymbolAddress((void**)&W2_l, g_W2_l);

    const int SM128 = 3 * (256 * 128);  // 98304
    const int SM64  = 3 * (192 * 128);  // 73728
    cudaFuncSetAttribute((const void*)mma_gemm3<128, 1, 0>,
                         cudaFuncAttributeMaxDynamicSharedMemorySize, SM128);
    cudaFuncSetAttribute((const void*)mma_gemm3<128, 1, 1>,
                         cudaFuncAttributeMaxDynamicSharedMemorySize, SM128);
    cudaFuncSetAttribute((const void*)mma_gemm3<128, 0, 0>,
                         cudaFuncAttributeMaxDynamicSharedMemorySize, SM128);
    cudaFuncSetAttribute((const void*)mma_gemm3<128, 2, 1>,
                         cudaFuncAttributeMaxDynamicSharedMemorySize, SM128);
    cudaFuncSetAttribute((const void*)mma_gemm3<64, 1, 0>,
                         cudaFuncAttributeMaxDynamicSharedMemorySize, SM64);

    // ---- conversions
    {
        int nEl = ROWS_QK * EE;
        int blocks = nEl / 4 / 256;
        conv_act<<<blocks, 256>>>(query, qin_h, qin_l, nEl);
        conv_act<<<blocks, 256>>>(key, kin_h, kin_l, nEl);
        conv_act<<<blocks, 256>>>(value, vin_h, vin_l, nEl);
        conv_wt<<<(EE * EE + 255) / 256, 256>>>(Wq, Wq_h, Wq_l, EE, EE);
        conv_wt<<<(EE * EE + 255) / 256, 256>>>(Wk, Wk_h, Wk_l, EE, EE);
        conv_wt<<<(EE * EE + 255) / 256, 256>>>(Wv, Wv_h, Wv_l, EE, EE);
        conv_wt<<<(EE * EE + 255) / 256, 256>>>(Wo, Wo_h, Wo_l, EE, EE);
        conv_wt<<<(64 * 128 + 255) / 256, 256>>>(W1, W1_h, W1_l, 64, 128);
        conv_wt<<<(128 * 64 + 255) / 256, 256>>>(W2, W2_h, W2_l, 128, 64);
    }

    // ---- projections
    {
        dim3 grid(EE / 128, ROWS_QK / 128);
        mma_gemm3<128, 1, 0><<<grid, 256, SM128>>>(
            qin_h, qin_l, Wq_h, Wq_l, bq, q_s, nullptr, nullptr, EE, EE, 0);
        mma_gemm3<128, 1, 1><<<grid, 256, SM128>>>(
            kin_h, kin_l, Wk_h, Wk_l, bk, nullptr, kact_h, kact_l, EE, EE, 64);
        mma_gemm3<128, 0, 0><<<grid, 256, SM128>>>(
            vin_h, vin_l, Wv_h, Wv_l, bv, v_s, nullptr, nullptr, EE, EE, 0);
    }
    // ---- key MLP
    {
        dim3 grid1(1, ROWS_MLP / 128);
        mma_gemm3<128, 2, 1><<<grid1, 256, SM128>>>(
            kact_h, kact_l, W1_h, W1_l, b1, nullptr, h1_h, h1_l, 128, 64, 128);
        mma_gemm3<64, 1, 0><<<grid1, 256, SM64>>>(
            h1_h, h1_l, W2_h, W2_l, b2, ka_s, nullptr, nullptr, 64, 128, 0);
    }
    // ---- kv context + ksum
    {
        int nz = BB * HH * DD * DD;
        zero_kernel<<<(nz + 255) / 256, 256>>>(kv_s, ksum_s);
        dim3 gkv(BB * HH, MMCTX / 256);
        kv_kernel<<<gkv, 256>>>(ka_s, v_s, kv_s);
        dim3 gks(BB * HH, MMCTX / 512);
        ksum_kernel<<<gks, 64>>>(ka_s, ksum_s);
    }
    // ---- out einsum + normalize -> attn hi/lo
    {
        size_t smem = (size_t)(HH * DD * DD + HH * DD) * sizeof(float);
        cudaFuncSetAttribute(out_kernel, cudaFuncAttributeMaxDynamicSharedMemorySize,
                             (int)smem);
        dim3 go(BB, NN / OUT_ROWS);
        out_kernel<<<go, 256, smem>>>(q_s, kv_s, ksum_s, attn_h, attn_l);
    }
    // ---- final projection
    {
        dim3 grid(EE / 128, ROWS_QK / 128);
        mma_gemm3<128, 0, 0><<<grid, 256, SM128>>>(
            attn_h, attn_l, Wo_h, Wo_l, bo, out, nullptr, nullptr, EE, EE, 0);
    }
}

// round 6
// speedup vs baseline: 2.6049x; 1.2695x over previous
#include <cuda_runtime.h>
#include <cuda_fp16.h>
#include <math.h>
#include <stdint.h>

#define BB 4
#define NN 4096
#define MMCTX 4096
#define EE 512
#define HH 8
#define DD 64
#define ROWS_QK (BB * NN)          // 16384
#define ROWS_MLP (BB * MMCTX * HH) // 131072

typedef __half h16;
typedef __half2 h162;

__device__ __forceinline__ uint32_t smem_u32(const void* p) {
    uint32_t a;
    asm("{ .reg .u64 t; cvta.to.shared.u64 t, %1; cvt.u32.u64 %0, t; }"
        : "=r"(a) : "l"(p));
    return a;
}

#define SWZ128(b) ((b) ^ (((b) >> 3) & 0x70))

__device__ __forceinline__ void cp_async16(uint32_t dst, const void* src) {
    asm volatile("cp.async.cg.shared.global [%0], [%1], 16;\n"
                 :: "r"(dst), "l"(src));
}
#define CP_COMMIT() asm volatile("cp.async.commit_group;\n" ::: "memory")
#define CP_WAIT1() asm volatile("cp.async.wait_group 1;\n" ::: "memory")
#define CP_WAIT0() asm volatile("cp.async.wait_group 0;\n" ::: "memory")

__device__ __forceinline__ void ldmatrix_x4(uint32_t addr, uint32_t& r0,
                                            uint32_t& r1, uint32_t& r2,
                                            uint32_t& r3) {
    asm volatile("ldmatrix.sync.aligned.m8n8.x4.shared.b16 {%0,%1,%2,%3}, [%4];"
                 : "=r"(r0), "=r"(r1), "=r"(r2), "=r"(r3) : "r"(addr));
}

__device__ __forceinline__ void mma16816(float* c, const uint32_t* a,
                                         const uint32_t* b) {
    asm volatile(
        "mma.sync.aligned.m16n8k16.row.col.f32.f16.f16.f32 "
        "{%0,%1,%2,%3}, {%4,%5,%6,%7}, {%8,%9}, {%0,%1,%2,%3};"
        : "+f"(c[0]), "+f"(c[1]), "+f"(c[2]), "+f"(c[3])
        : "r"(a[0]), "r"(a[1]), "r"(a[2]), "r"(a[3]), "r"(b[0]), "r"(b[1]));
}

// ===================== scratch =====================
__device__ float g_q[ROWS_QK * EE];
__device__ float g_v[ROWS_QK * EE];
__device__ float g_ka[ROWS_MLP * DD];
__device__ float g_kv[BB * HH * DD * DD];
__device__ float g_ksum[BB * HH * DD];

__device__ h16 g_qin_h[ROWS_QK * EE], g_qin_l[ROWS_QK * EE];
__device__ h16 g_kin_h[ROWS_QK * EE], g_kin_l[ROWS_QK * EE];
__device__ h16 g_vin_h[ROWS_QK * EE], g_vin_l[ROWS_QK * EE];
__device__ h16 g_kact_h[ROWS_MLP * DD], g_kact_l[ROWS_MLP * DD];
__device__ h16 g_h1_h[ROWS_MLP * 128], g_h1_l[ROWS_MLP * 128];
__device__ h16 g_attn_h[ROWS_QK * EE], g_attn_l[ROWS_QK * EE];

__device__ h16 g_Wq[EE * EE];
__device__ h16 g_Wk[EE * EE];
__device__ h16 g_Wv[EE * EE];
__device__ h16 g_Wo[EE * EE];
__device__ h16 g_W1[128 * 64];
__device__ h16 g_W2[64 * 128];

// ===================== conversions =====================
__global__ void conv_act(const float* __restrict__ x, h16* __restrict__ hi,
                         h16* __restrict__ lo, int n) {
    int i = (blockIdx.x * blockDim.x + threadIdx.x) * 4;
    if (i >= n) return;
    float4 v = *(const float4*)&x[i];
    h16 h0 = __float2half(v.x), h1 = __float2half(v.y);
    h16 h2 = __float2half(v.z), h3 = __float2half(v.w);
    h16 l0 = __float2half(v.x - __half2float(h0));
    h16 l1 = __float2half(v.y - __half2float(h1));
    h16 l2 = __float2half(v.z - __half2float(h2));
    h16 l3 = __float2half(v.w - __half2float(h3));
    h162 a; a.x = h0; a.y = h1;
    h162 b; b.x = h2; b.y = h3;
    h162 c; c.x = l0; c.y = l1;
    h162 d; d.x = l2; d.y = l3;
    *(h162*)&hi[i] = a; *(h162*)&hi[i + 2] = b;
    *(h162*)&lo[i] = c; *(h162*)&lo[i + 2] = d;
}

// W[k*N+n] -> Wt[n*K+k] single fp16
__global__ void conv_wt(const float* __restrict__ W, h16* __restrict__ o,
                        int K, int N) {
    int idx = blockIdx.x * blockDim.x + threadIdx.x;
    if (idx >= K * N) return;
    int k = idx / N, n = idx % N;
    o[n * K + k] = __float2half(W[idx]);
}

// ===================== HMMA fp16 2-pass GEMM =====================
// C[M,N] = epi(A @ W^T + bias): A = Ah+Al fp16 [M,K] row-major; B fp16 [N,K].
// EPI: 0 none, 1 elu+1, 2 gelu. OUTM: 0 -> Cf fp32; 1 -> Chi/Clo fp16, remap CK.
template <int BN, int EPI, int OUTM>
__global__ void __launch_bounds__(256, 2)
mma_gemm2(const h16* __restrict__ Ah, const h16* __restrict__ Al,
          const h16* __restrict__ B, const float* __restrict__ bias,
          float* __restrict__ Cf, h16* __restrict__ Chi, h16* __restrict__ Clo,
          int Ntot, int K, int CK) {
    extern __shared__ char sm[];
    // stage: A_hi 128x128B (16K) | A_lo 16K | B BN x 128B
    constexpr int A_T = 128 * 128;
    constexpr int STAGE = 2 * A_T + BN * 128;
    constexpr int NT = (BN == 128) ? 8 : 4;
    constexpr int WNW = NT * 8;

    const int tid = threadIdx.x;
    const int lane = tid & 31, wid = tid >> 5;
    const int wm = wid >> 1, wn = wid & 1;
    const int row0 = blockIdx.y * 128;
    const int col0 = blockIdx.x * BN;
    const uint32_t smb = smem_u32(sm);
    const int nc = K / 64;

    float acc[2][NT][4];
#pragma unroll
    for (int i = 0; i < 2; i++)
#pragma unroll
        for (int j = 0; j < NT; j++)
#pragma unroll
            for (int t = 0; t < 4; t++) acc[i][j][t] = 0.f;

    auto load_stage = [&](int c, int buf) {
        uint32_t as = smb + buf * STAGE;
        uint32_t bs = as + 2 * A_T;
        const h16* Aph = Ah + (size_t)row0 * K + c * 64;
        const h16* Apl = Al + (size_t)row0 * K + c * 64;
        const h16* Bp = B + (size_t)col0 * K + c * 64;
        // A hi+lo: 128 rows x 8 segs of 16B each
#pragma unroll
        for (int i = 0; i < 4; i++) {
            int idx = tid + i * 256;
            int r = idx >> 3, u = idx & 7;
            uint32_t so = SWZ128((uint32_t)(r * 128 + u * 16));
            cp_async16(as + so, Aph + (size_t)r * K + u * 8);
            cp_async16(as + A_T + so, Apl + (size_t)r * K + u * 8);
        }
        // B: BN rows x 8 segs
#pragma unroll
        for (int i = 0; i < BN / 32; i++) {
            int idx = tid + i * 256;
            int r = idx >> 3, u = idx & 7;
            cp_async16(bs + SWZ128((uint32_t)(r * 128 + u * 16)),
                       Bp + (size_t)r * K + u * 8);
        }
    };

    load_stage(0, 0);
    CP_COMMIT();

    for (int c = 0; c < nc; c++) {
        if (c + 1 < nc) {
            load_stage(c + 1, (c + 1) & 1);
            CP_COMMIT();
            CP_WAIT1();
        } else {
            CP_WAIT0();
        }
        __syncthreads();
        uint32_t as = smb + (c & 1) * STAGE;
        uint32_t bs = as + 2 * A_T;
#pragma unroll
        for (int ks = 0; ks < 4; ks++) {
            uint32_t ah[2][4], al[2][4], bb[NT][2];
#pragma unroll
            for (int mt = 0; mt < 2; mt++) {
                int row = wm * 32 + mt * 16 + (lane & 15);
                int kb = ks * 32 + ((lane >> 4) << 4);
                uint32_t so = SWZ128((uint32_t)(row * 128 + kb));
                ldmatrix_x4(as + so, ah[mt][0], ah[mt][1], ah[mt][2], ah[mt][3]);
                ldmatrix_x4(as + A_T + so, al[mt][0], al[mt][1], al[mt][2],
                            al[mt][3]);
            }
#pragma unroll
            for (int p = 0; p < NT / 2; p++) {
                int row = wn * WNW + p * 16 + ((lane >> 4) << 3) + (lane & 7);
                int kb = ks * 32 + (((lane & 15) >> 3) << 4);
                ldmatrix_x4(bs + SWZ128((uint32_t)(row * 128 + kb)),
                            bb[2 * p][0], bb[2 * p][1], bb[2 * p + 1][0],
                            bb[2 * p + 1][1]);
            }
#pragma unroll
            for (int mt = 0; mt < 2; mt++)
#pragma unroll
                for (int nt = 0; nt < NT; nt++) mma16816(acc[mt][nt], ah[mt], bb[nt]);
#pragma unroll
            for (int mt = 0; mt < 2; mt++)
#pragma unroll
                for (int nt = 0; nt < NT; nt++) mma16816(acc[mt][nt], al[mt], bb[nt]);
        }
        __syncthreads();
    }

    // ---- epilogue ----
    const int EPR = (OUTM == 1) ? (Ntot / CK) : 1;
#pragma unroll
    for (int mt = 0; mt < 2; mt++) {
#pragma unroll
        for (int nt = 0; nt < NT; nt++) {
            int col = col0 + wn * WNW + nt * 8 + 2 * (lane & 3);
            float bia0 = bias[col], bia1 = bias[col + 1];
#pragma unroll
            for (int half = 0; half < 2; half++) {
                int row = row0 + wm * 32 + mt * 16 + (lane >> 2) + half * 8;
                float v0 = acc[mt][nt][half * 2 + 0] + bia0;
                float v1 = acc[mt][nt][half * 2 + 1] + bia1;
                if (EPI == 1) {
                    v0 = (v0 > 0.f) ? (v0 + 1.f) : expf(v0);
                    v1 = (v1 > 0.f) ? (v1 + 1.f) : expf(v1);
                } else if (EPI == 2) {
                    v0 = 0.5f * v0 * (1.f + erff(v0 * 0.70710678118654752f));
                    v1 = 0.5f * v1 * (1.f + erff(v1 * 0.70710678118654752f));
                }
                if (OUTM == 0) {
                    float2 o = make_float2(v0, v1);
                    *(float2*)&Cf[(size_t)row * Ntot + col] = o;
                } else {
                    h16 h0 = __float2half(v0);
                    h16 h1 = __float2half(v1);
                    h16 l0 = __float2half(v0 - __half2float(h0));
                    h16 l1 = __float2half(v1 - __half2float(h1));
                    int rp = row * EPR + col / CK;
                    int cp = col % CK;
                    size_t base = (size_t)rp * CK + cp;
                    h162 ph; ph.x = h0; ph.y = h1;
                    h162 pl; pl.x = l0; pl.y = l1;
                    *(h162*)&Chi[base] = ph;
                    *(h162*)&Clo[base] = pl;
                }
            }
        }
    }
}

// ===================== zero =====================
__global__ void zero_kernel(float* __restrict__ kv, float* __restrict__ ksum) {
    int i = blockIdx.x * blockDim.x + threadIdx.x;
    if (i < BB * HH * DD * DD) kv[i] = 0.f;
    if (i < BB * HH * DD) ksum[i] = 0.f;
}

// ===================== kv context (fused ksum) =====================
__global__ void kv_kernel(const float* __restrict__ ka, const float* __restrict__ v,
                          float* __restrict__ kv, float* __restrict__ ksum) {
    const int bh = blockIdx.x;
    const int b = bh / HH, h = bh % HH;
    const int m0 = blockIdx.y * 256;
    __shared__ float ka_s[16][64];
    __shared__ float v_s[16][64];
    const int tid = threadIdx.x;
    const int tx = tid % 16, ty = tid / 16;
    float acc[4][4];
    float ksm[4] = {0.f, 0.f, 0.f, 0.f};
#pragma unroll
    for (int i = 0; i < 4; i++)
#pragma unroll
        for (int j = 0; j < 4; j++) acc[i][j] = 0.f;
    const size_t base = (size_t)b * MMCTX * EE + (size_t)h * DD;
    for (int mt = 0; mt < 16; mt++) {
        const int m = m0 + mt * 16;
        {
            int mm = tid / 16, e4 = tid % 16;
            size_t g = base + (size_t)(m + mm) * EE + e4 * 4;
            float4 kav = *(const float4*)&ka[g];
            *(float4*)&ka_s[mm][e4 * 4] = kav;
            ksm[0] += kav.x; ksm[1] += kav.y; ksm[2] += kav.z; ksm[3] += kav.w;
            *(float4*)&v_s[mm][e4 * 4] = *(const float4*)&v[g];
        }
        __syncthreads();
#pragma unroll
        for (int mm = 0; mm < 16; mm++) {
            float rd[4];
            float4 re = *(const float4*)&v_s[mm][tx * 4];
#pragma unroll
            for (int i = 0; i < 4; i++) rd[i] = ka_s[mm][ty * 4 + i];
#pragma unroll
            for (int i = 0; i < 4; i++) {
                acc[i][0] += rd[i] * re.x; acc[i][1] += rd[i] * re.y;
                acc[i][2] += rd[i] * re.z; acc[i][3] += rd[i] * re.w;
            }
        }
        __syncthreads();
    }
    const float inv_m = 1.f / (float)MMCTX;
#pragma unroll
    for (int i = 0; i < 4; i++)
#pragma unroll
        for (int j = 0; j < 4; j++)
            atomicAdd(&kv[((size_t)bh * DD + ty * 4 + i) * DD + tx * 4 + j],
                      acc[i][j] * inv_m);
    {
        int e4 = tid % 16;
#pragma unroll
        for (int j = 0; j < 4; j++)
            atomicAdd(&ksum[bh * DD + e4 * 4 + j], ksm[j] * inv_m);
    }
}

// ===================== out einsum + normalize -> attn hi/lo =====================
#define OUT_ROWS 32
__global__ void out_kernel(const float* __restrict__ q, const float* __restrict__ kv,
                           const float* __restrict__ ksum,
                           h16* __restrict__ attn_h, h16* __restrict__ attn_l) {
    extern __shared__ float smf[];
    float* kv_s = smf;
    float* ks_s = smf + HH * DD * DD;
    const int b = blockIdx.x;
    const int r0 = blockIdx.y * OUT_ROWS;
    const int tid = threadIdx.x;
    for (int i = tid; i < HH * DD * DD / 4; i += 256)
        *(float4*)&kv_s[i * 4] = *(const float4*)&kv[(size_t)b * HH * DD * DD + i * 4];
    for (int i = tid; i < HH * DD / 4; i += 256)
        *(float4*)&ks_s[i * 4] = *(const float4*)&ksum[b * HH * DD + i * 4];
    __syncthreads();
    const int h = tid / 32, lane = tid % 32;
    const float* kvh = &kv_s[h * DD * DD];
    for (int r = 0; r < OUT_ROWS; r++) {
        const int n = r0 + r;
        const size_t row = (size_t)b * NN + n;
        const size_t qb = row * EE + h * DD;
        float q0 = q[qb + lane];
        float q1 = q[qb + lane + 32];
        float dp = q0 * ks_s[h * DD + lane] + q1 * ks_s[h * DD + lane + 32];
#pragma unroll
        for (int off = 16; off; off >>= 1) dp += __shfl_xor_sync(0xffffffffu, dp, off);
        dp = fmaxf(dp, 1e-6f);
        float a0 = 0.f, a1 = 0.f;
#pragma unroll
        for (int d = 0; d < DD; d++) {
            float qd = __shfl_sync(0xffffffffu, (d < 32) ? q0 : q1, d & 31);
            float2 kvv = *(const float2*)&kvh[d * DD + lane * 2];
            a0 += qd * kvv.x;
            a1 += qd * kvv.y;
        }
        a0 /= dp; a1 /= dp;
        a0 = isnan(a0) ? 0.f : fminf(fmaxf(a0, -65000.f), 65000.f);
        a1 = isnan(a1) ? 0.f : fminf(fmaxf(a1, -65000.f), 65000.f);
        h16 h0 = __float2half(a0), h1 = __float2half(a1);
        h16 l0 = __float2half(a0 - __half2float(h0));
        h16 l1 = __float2half(a1 - __half2float(h1));
        h162 ph; ph.x = h0; ph.y = h1;
        h162 pl; pl.x = l0; pl.y = l1;
        *(h162*)&attn_h[qb + lane * 2] = ph;
        *(h162*)&attn_l[qb + lane * 2] = pl;
    }
}

// ===================== launch =====================
extern "C" void kernel_launch(void* const* d_in, const int* in_sizes, int n_in,
                              void* d_out, int out_size) {
    const float* query = (const float*)d_in[0];
    const float* key   = (const float*)d_in[1];
    const float* value = (const float*)d_in[2];
    const float* Wq = (const float*)d_in[3];
    const float* bq = (const float*)d_in[4];
    const float* Wk = (const float*)d_in[5];
    const float* bk = (const float*)d_in[6];
    const float* Wv = (const float*)d_in[7];
    const float* bv = (const float*)d_in[8];
    const float* W1 = (const float*)d_in[9];
    const float* b1 = (const float*)d_in[10];
    const float* W2 = (const float*)d_in[11];
    const float* b2 = (const float*)d_in[12];
    const float* Wo = (const float*)d_in[13];
    const float* bo = (const float*)d_in[14];
    float* out = (float*)d_out;

    float *q_s, *v_s, *ka_s, *kv_s, *ksum_s;
    cudaGetSymbolAddress((void**)&q_s, g_q);
    cudaGetSymbolAddress((void**)&v_s, g_v);
    cudaGetSymbolAddress((void**)&ka_s, g_ka);
    cudaGetSymbolAddress((void**)&kv_s, g_kv);
    cudaGetSymbolAddress((void**)&ksum_s, g_ksum);

    h16 *qin_h, *qin_l, *kin_h, *kin_l, *vin_h, *vin_l;
    h16 *kact_h, *kact_l, *h1_h, *h1_l, *attn_h, *attn_l;
    h16 *Wqd, *Wkd, *Wvd, *Wod, *W1d, *W2d;
    cudaGetSymbolAddress((void**)&qin_h, g_qin_h);
    cudaGetSymbolAddress((void**)&qin_l, g_qin_l);
    cudaGetSymbolAddress((void**)&kin_h, g_kin_h);
    cudaGetSymbolAddress((void**)&kin_l, g_kin_l);
    cudaGetSymbolAddress((void**)&vin_h, g_vin_h);
    cudaGetSymbolAddress((void**)&vin_l, g_vin_l);
    cudaGetSymbolAddress((void**)&kact_h, g_kact_h);
    cudaGetSymbolAddress((void**)&kact_l, g_kact_l);
    cudaGetSymbolAddress((void**)&h1_h, g_h1_h);
    cudaGetSymbolAddress((void**)&h1_l, g_h1_l);
    cudaGetSymbolAddress((void**)&attn_h, g_attn_h);
    cudaGetSymbolAddress((void**)&attn_l, g_attn_l);
    cudaGetSymbolAddress((void**)&Wqd, g_Wq);
    cudaGetSymbolAddress((void**)&Wkd, g_Wk);
    cudaGetSymbolAddress((void**)&Wvd, g_Wv);
    cudaGetSymbolAddress((void**)&Wod, g_Wo);
    cudaGetSymbolAddress((void**)&W1d, g_W1);
    cudaGetSymbolAddress((void**)&W2d, g_W2);

    const int SM128 = 2 * (2 * 16384 + 128 * 128);  // 98304
    const int SM64  = 2 * (2 * 16384 + 64 * 128);   // 81920
    cudaFuncSetAttribute((const void*)mma_gemm2<128, 1, 0>,
                         cudaFuncAttributeMaxDynamicSharedMemorySize, SM128);
    cudaFuncSetAttribute((const void*)mma_gemm2<128, 1, 1>,
                         cudaFuncAttributeMaxDynamicSharedMemorySize, SM128);
    cudaFuncSetAttribute((const void*)mma_gemm2<128, 0, 0>,
                         cudaFuncAttributeMaxDynamicSharedMemorySize, SM128);
    cudaFuncSetAttribute((const void*)mma_gemm2<128, 2, 1>,
                         cudaFuncAttributeMaxDynamicSharedMemorySize, SM128);
    cudaFuncSetAttribute((const void*)mma_gemm2<64, 1, 0>,
                         cudaFuncAttributeMaxDynamicSharedMemorySize, SM64);

    // ---- conversions
    {
        int nEl = ROWS_QK * EE;
        int blocks = nEl / 4 / 256;
        conv_act<<<blocks, 256>>>(query, qin_h, qin_l, nEl);
        conv_act<<<blocks, 256>>>(key, kin_h, kin_l, nEl);
        conv_act<<<blocks, 256>>>(value, vin_h, vin_l, nEl);
        conv_wt<<<(EE * EE + 255) / 256, 256>>>(Wq, Wqd, EE, EE);
        conv_wt<<<(EE * EE + 255) / 256, 256>>>(Wk, Wkd, EE, EE);
        conv_wt<<<(EE * EE + 255) / 256, 256>>>(Wv, Wvd, EE, EE);
        conv_wt<<<(EE * EE + 255) / 256, 256>>>(Wo, Wod, EE, EE);
        conv_wt<<<(64 * 128 + 255) / 256, 256>>>(W1, W1d, 64, 128);
        conv_wt<<<(128 * 64 + 255) / 256, 256>>>(W2, W2d, 128, 64);
    }

    // ---- projections
    {
        dim3 grid(EE / 128, ROWS_QK / 128);
        mma_gemm2<128, 1, 0><<<grid, 256, SM128>>>(
            qin_h, qin_l, Wqd, bq, q_s, nullptr, nullptr, EE, EE, 0);
        mma_gemm2<128, 1, 1><<<grid, 256, SM128>>>(
            kin_h, kin_l, Wkd, bk, nullptr, kact_h, kact_l, EE, EE, 64);
        mma_gemm2<128, 0, 0><<<grid, 256, SM128>>>(
            vin_h, vin_l, Wvd, bv, v_s, nullptr, nullptr, EE, EE, 0);
    }
    // ---- key MLP
    {
        dim3 grid1(1, ROWS_MLP / 128);
        mma_gemm2<128, 2, 1><<<grid1, 256, SM128>>>(
            kact_h, kact_l, W1d, b1, nullptr, h1_h, h1_l, 128, 64, 128);
        mma_gemm2<64, 1, 0><<<grid1, 256, SM64>>>(
            h1_h, h1_l, W2d, b2, ka_s, nullptr, nullptr, 64, 128, 0);
    }
    // ---- kv context + fused ksum
    {
        int nz = BB * HH * DD * DD;
        zero_kernel<<<(nz + 255) / 256, 256>>>(kv_s, ksum_s);
        dim3 gkv(BB * HH, MMCTX / 256);
        kv_kernel<<<gkv, 256>>>(ka_s, v_s, kv_s, ksum_s);
    }
    // ---- out einsum + normalize -> attn hi/lo
    {
        size_t smem = (size_t)(HH * DD * DD + HH * DD) * sizeof(float);
        cudaFuncSetAttribute(out_kernel, cudaFuncAttributeMaxDynamicSharedMemorySize,
                             (int)smem);
        dim3 go(BB, NN / OUT_ROWS);
        out_kernel<<<go, 256, smem>>>(q_s, kv_s, ksum_s, attn_h, attn_l);
    }
    // ---- final projection
    {
        dim3 grid(EE / 128, ROWS_QK / 128);
        mma_gemm2<128, 0, 0><<<grid, 256, SM128>>>(
            attn_h, attn_l, Wod, bo, out, nullptr, nullptr, EE, EE, 0);
    }
}

// round 7
// speedup vs baseline: 2.6757x; 1.0272x over previous
#include <cuda_runtime.h>
#include <cuda_fp16.h>
#include <math.h>
#include <stdint.h>

#define BB 4
#define NN 4096
#define MMCTX 4096
#define EE 512
#define HH 8
#define DD 64
#define ROWS_QK (BB * NN)          // 16384
#define ROWS_MLP (BB * MMCTX * HH) // 131072

typedef __half h16;
typedef __half2 h162;

__device__ __forceinline__ uint32_t smem_u32(const void* p) {
    uint32_t a;
    asm("{ .reg .u64 t; cvta.to.shared.u64 t, %1; cvt.u32.u64 %0, t; }"
        : "=r"(a) : "l"(p));
    return a;
}

#define SWZ128(b) ((b) ^ (((b) >> 3) & 0x70))

__device__ __forceinline__ void cp_async16(uint32_t dst, const void* src) {
    asm volatile("cp.async.cg.shared.global [%0], [%1], 16;\n"
                 :: "r"(dst), "l"(src));
}
#define CP_COMMIT() asm volatile("cp.async.commit_group;\n" ::: "memory")
#define CP_WAIT1() asm volatile("cp.async.wait_group 1;\n" ::: "memory")
#define CP_WAIT0() asm volatile("cp.async.wait_group 0;\n" ::: "memory")

__device__ __forceinline__ void ldmatrix_x4(uint32_t addr, uint32_t& r0,
                                            uint32_t& r1, uint32_t& r2,
                                            uint32_t& r3) {
    asm volatile("ldmatrix.sync.aligned.m8n8.x4.shared.b16 {%0,%1,%2,%3}, [%4];"
                 : "=r"(r0), "=r"(r1), "=r"(r2), "=r"(r3) : "r"(addr));
}

__device__ __forceinline__ void mma16816(float* c, const uint32_t* a,
                                         const uint32_t* b) {
    asm volatile(
        "mma.sync.aligned.m16n8k16.row.col.f32.f16.f16.f32 "
        "{%0,%1,%2,%3}, {%4,%5,%6,%7}, {%8,%9}, {%0,%1,%2,%3};"
        : "+f"(c[0]), "+f"(c[1]), "+f"(c[2]), "+f"(c[3])
        : "r"(a[0]), "r"(a[1]), "r"(a[2]), "r"(a[3]), "r"(b[0]), "r"(b[1]));
}

// ===================== scratch =====================
__device__ float g_q[ROWS_QK * EE];
__device__ float g_v[ROWS_QK * EE];
__device__ float g_ka[ROWS_MLP * DD];
__device__ float g_kv[BB * HH * DD * DD];
__device__ float g_ksum[BB * HH * DD];

__device__ h16 g_kact_h[ROWS_MLP * DD], g_kact_l[ROWS_MLP * DD];
__device__ h16 g_attn_h[ROWS_QK * EE], g_attn_l[ROWS_QK * EE];

__device__ h16 g_Wq[EE * EE];
__device__ h16 g_Wk[EE * EE];
__device__ h16 g_Wv[EE * EE];
__device__ h16 g_Wo[EE * EE];
__device__ h16 g_W1[128 * 64];
__device__ h16 g_W2[64 * 128];

// ===================== weight conversion =====================
// W[k*N+n] -> Wt[n*K+k] single fp16
__global__ void conv_wt(const float* __restrict__ W, h16* __restrict__ o,
                        int K, int N) {
    int idx = blockIdx.x * blockDim.x + threadIdx.x;
    if (idx >= K * N) return;
    int k = idx / N, n = idx % N;
    o[n * K + k] = __float2half(W[idx]);
}

// ===================== epilogue helper (shared between GEMMs) ==============
__device__ __forceinline__ float apply_epi(float v, int EPI) {
    if (EPI == 1) return (v > 0.f) ? (v + 1.f) : expf(v);
    if (EPI == 2) return 0.5f * v * (1.f + erff(v * 0.70710678118654752f));
    return v;
}

// ===================== converting fp32-A HMMA GEMM (BN=128, BK=32) =========
// C[M,128-col-tile] = epi(A @ W^T + bias): A fp32 [M,K] row-major;
// B fp16 [N,K]. 2-pass hi/lo split of A done in-kernel.
// OUTM: 0 -> Cf fp32 [M,Ntot]; 1 -> Chi/Clo fp16, row remap chunk CK.
template <int EPI, int OUTM>
__global__ void __launch_bounds__(256, 2)
mma_gemmF(const float* __restrict__ A, const h16* __restrict__ B,
          const float* __restrict__ bias, float* __restrict__ Cf,
          h16* __restrict__ Chi, h16* __restrict__ Clo, int Ntot, int K,
          int CK) {
    extern __shared__ char sm[];
    // layout: A32 2x16K @0 ; B 2x16K @32768 ; conv hi/lo 16K @65536
    const int tid = threadIdx.x;
    const int lane = tid & 31, wid = tid >> 5;
    const int wm = wid >> 1, wn = wid & 1;
    const int row0 = blockIdx.y * 128;
    const int col0 = blockIdx.x * 128;
    const uint32_t smb = smem_u32(sm);
    const int nc = K / 32;

    float acc[2][8][4];
#pragma unroll
    for (int i = 0; i < 2; i++)
#pragma unroll
        for (int j = 0; j < 8; j++)
#pragma unroll
            for (int t = 0; t < 4; t++) acc[i][j][t] = 0.f;

    auto load_stage = [&](int c, int buf) {
        uint32_t as = smb + buf * 16384;
        uint32_t bs = smb + 32768 + buf * 16384;
        const float* Ap = A + (size_t)row0 * K + c * 32;
        const h16* Bp = B + (size_t)col0 * K + c * 32;
#pragma unroll
        for (int i = 0; i < 4; i++) {
            int idx = tid + i * 256;
            int r = idx >> 3, u = idx & 7;
            cp_async16(as + SWZ128((uint32_t)(r * 128 + u * 16)),
                       Ap + (size_t)r * K + u * 4);
        }
#pragma unroll
        for (int i = 0; i < 2; i++) {
            int idx = tid + i * 256;
            int r = idx >> 2, u = idx & 3;
            cp_async16(bs + SWZ128((uint32_t)(r * 128 + u * 16)),
                       Bp + (size_t)r * K + u * 8);
        }
    };

    load_stage(0, 0);
    CP_COMMIT();

    for (int c = 0; c < nc; c++) {
        if (c + 1 < nc) {
            load_stage(c + 1, (c + 1) & 1);
            CP_COMMIT();
            CP_WAIT1();
        } else {
            CP_WAIT0();
        }
        // convert own segs: A32[c&1] fp32 -> conv hi/lo fp16
        {
            char* ap = sm + (c & 1) * 16384;
            char* cvp = sm + 65536;
#pragma unroll
            for (int i = 0; i < 4; i++) {
                int idx = tid + i * 256;
                int r = idx >> 3, u = idx & 7;
                float4 v4 = *(const float4*)(ap + SWZ128((uint32_t)(r * 128 + u * 16)));
                h16 h0 = __float2half(v4.x), h1 = __float2half(v4.y);
                h16 h2 = __float2half(v4.z), h3 = __float2half(v4.w);
                h16 l0 = __float2half(v4.x - __half2float(h0));
                h16 l1 = __float2half(v4.y - __half2float(h1));
                h16 l2 = __float2half(v4.z - __half2float(h2));
                h16 l3 = __float2half(v4.w - __half2float(h3));
                h162 p0; p0.x = h0; p0.y = h1;
                h162 p1; p1.x = h2; p1.y = h3;
                h162 q0; q0.x = l0; q0.y = l1;
                h162 q1; q1.x = l2; q1.y = l3;
                uint32_t dhi = SWZ128((uint32_t)(r * 128 + u * 8));
                uint32_t dlo = SWZ128((uint32_t)(r * 128 + 64 + u * 8));
                *(h162*)(cvp + dhi) = p0;
                *(h162*)(cvp + dhi + 4) = p1;
                *(h162*)(cvp + dlo) = q0;
                *(h162*)(cvp + dlo + 4) = q1;
            }
        }
        __syncthreads();
        const uint32_t cvb = smb + 65536;
        const uint32_t bsb = smb + 32768 + (c & 1) * 16384;
#pragma unroll
        for (int ks = 0; ks < 2; ks++) {
            uint32_t ah[2][4], al[2][4], bb[8][2];
#pragma unroll
            for (int mt = 0; mt < 2; mt++) {
                int row = wm * 32 + mt * 16 + (lane & 15);
                int kb = ks * 32 + ((lane >> 4) << 4);
                ldmatrix_x4(cvb + SWZ128((uint32_t)(row * 128 + kb)),
                            ah[mt][0], ah[mt][1], ah[mt][2], ah[mt][3]);
                ldmatrix_x4(cvb + SWZ128((uint32_t)(row * 128 + 64 + kb)),
                            al[mt][0], al[mt][1], al[mt][2], al[mt][3]);
            }
#pragma unroll
            for (int p = 0; p < 4; p++) {
                int row = wn * 64 + p * 16 + ((lane >> 4) << 3) + (lane & 7);
                int kb = ks * 32 + (((lane & 15) >> 3) << 4);
                ldmatrix_x4(bsb + SWZ128((uint32_t)(row * 128 + kb)),
                            bb[2 * p][0], bb[2 * p][1], bb[2 * p + 1][0],
                            bb[2 * p + 1][1]);
            }
#pragma unroll
            for (int mt = 0; mt < 2; mt++)
#pragma unroll
                for (int nt = 0; nt < 8; nt++) mma16816(acc[mt][nt], ah[mt], bb[nt]);
#pragma unroll
            for (int mt = 0; mt < 2; mt++)
#pragma unroll
                for (int nt = 0; nt < 8; nt++) mma16816(acc[mt][nt], al[mt], bb[nt]);
        }
        __syncthreads();
    }

    // ---- epilogue ----
    const int EPR = (OUTM == 1) ? (Ntot / CK) : 1;
#pragma unroll
    for (int mt = 0; mt < 2; mt++) {
#pragma unroll
        for (int nt = 0; nt < 8; nt++) {
            int col = col0 + wn * 64 + nt * 8 + 2 * (lane & 3);
            float bia0 = bias[col], bia1 = bias[col + 1];
#pragma unroll
            for (int half = 0; half < 2; half++) {
                int row = row0 + wm * 32 + mt * 16 + (lane >> 2) + half * 8;
                float v0 = apply_epi(acc[mt][nt][half * 2 + 0] + bia0, EPI);
                float v1 = apply_epi(acc[mt][nt][half * 2 + 1] + bia1, EPI);
                if (OUTM == 0) {
                    float2 o = make_float2(v0, v1);
                    *(float2*)&Cf[(size_t)row * Ntot + col] = o;
                } else {
                    h16 h0 = __float2half(v0);
                    h16 h1 = __float2half(v1);
                    h16 l0 = __float2half(v0 - __half2float(h0));
                    h16 l1 = __float2half(v1 - __half2float(h1));
                    int rp = row * EPR + col / CK;
                    int cp = col % CK;
                    size_t base = (size_t)rp * CK + cp;
                    h162 ph; ph.x = h0; ph.y = h1;
                    h162 pl; pl.x = l0; pl.y = l1;
                    *(h162*)&Chi[base] = ph;
                    *(h162*)&Clo[base] = pl;
                }
            }
        }
    }
}

// ===================== non-converting HMMA GEMM (for attn @ Wo) ============
__global__ void __launch_bounds__(256, 2)
mma_gemm2(const h16* __restrict__ Ah, const h16* __restrict__ Al,
          const h16* __restrict__ B, const float* __restrict__ bias,
          float* __restrict__ Cf, int Ntot, int K) {
    extern __shared__ char sm[];
    constexpr int A_T = 128 * 128;
    constexpr int STAGE = 2 * A_T + 128 * 128;
    const int tid = threadIdx.x;
    const int lane = tid & 31, wid = tid >> 5;
    const int wm = wid >> 1, wn = wid & 1;
    const int row0 = blockIdx.y * 128;
    const int col0 = blockIdx.x * 128;
    const uint32_t smb = smem_u32(sm);
    const int nc = K / 64;

    float acc[2][8][4];
#pragma unroll
    for (int i = 0; i < 2; i++)
#pragma unroll
        for (int j = 0; j < 8; j++)
#pragma unroll
            for (int t = 0; t < 4; t++) acc[i][j][t] = 0.f;

    auto load_stage = [&](int c, int buf) {
        uint32_t as = smb + buf * STAGE;
        uint32_t bs = as + 2 * A_T;
        const h16* Aph = Ah + (size_t)row0 * K + c * 64;
        const h16* Apl = Al + (size_t)row0 * K + c * 64;
        const h16* Bp = B + (size_t)col0 * K + c * 64;
#pragma unroll
        for (int i = 0; i < 4; i++) {
            int idx = tid + i * 256;
            int r = idx >> 3, u = idx & 7;
            uint32_t so = SWZ128((uint32_t)(r * 128 + u * 16));
            cp_async16(as + so, Aph + (size_t)r * K + u * 8);
            cp_async16(as + A_T + so, Apl + (size_t)r * K + u * 8);
        }
#pragma unroll
        for (int i = 0; i < 4; i++) {
            int idx = tid + i * 256;
            int r = idx >> 3, u = idx & 7;
            cp_async16(bs + SWZ128((uint32_t)(r * 128 + u * 16)),
                       Bp + (size_t)r * K + u * 8);
        }
    };

    load_stage(0, 0);
    CP_COMMIT();

    for (int c = 0; c < nc; c++) {
        if (c + 1 < nc) {
            load_stage(c + 1, (c + 1) & 1);
            CP_COMMIT();
            CP_WAIT1();
        } else {
            CP_WAIT0();
        }
        __syncthreads();
        uint32_t as = smb + (c & 1) * STAGE;
        uint32_t bs = as + 2 * A_T;
#pragma unroll
        for (int ks = 0; ks < 4; ks++) {
            uint32_t ah[2][4], al[2][4], bb[8][2];
#pragma unroll
            for (int mt = 0; mt < 2; mt++) {
                int row = wm * 32 + mt * 16 + (lane & 15);
                int kb = ks * 32 + ((lane >> 4) << 4);
                uint32_t so = SWZ128((uint32_t)(row * 128 + kb));
                ldmatrix_x4(as + so, ah[mt][0], ah[mt][1], ah[mt][2], ah[mt][3]);
                ldmatrix_x4(as + A_T + so, al[mt][0], al[mt][1], al[mt][2],
                            al[mt][3]);
            }
#pragma unroll
            for (int p = 0; p < 4; p++) {
                int row = wn * 64 + p * 16 + ((lane >> 4) << 3) + (lane & 7);
                int kb = ks * 32 + (((lane & 15) >> 3) << 4);
                ldmatrix_x4(bs + SWZ128((uint32_t)(row * 128 + kb)),
                            bb[2 * p][0], bb[2 * p][1], bb[2 * p + 1][0],
                            bb[2 * p + 1][1]);
            }
#pragma unroll
            for (int mt = 0; mt < 2; mt++)
#pragma unroll
                for (int nt = 0; nt < 8; nt++) mma16816(acc[mt][nt], ah[mt], bb[nt]);
#pragma unroll
            for (int mt = 0; mt < 2; mt++)
#pragma unroll
                for (int nt = 0; nt < 8; nt++) mma16816(acc[mt][nt], al[mt], bb[nt]);
        }
        __syncthreads();
    }

#pragma unroll
    for (int mt = 0; mt < 2; mt++) {
#pragma unroll
        for (int nt = 0; nt < 8; nt++) {
            int col = col0 + wn * 64 + nt * 8 + 2 * (lane & 3);
            float bia0 = bias[col], bia1 = bias[col + 1];
#pragma unroll
            for (int half = 0; half < 2; half++) {
                int row = row0 + wm * 32 + mt * 16 + (lane >> 2) + half * 8;
                float v0 = acc[mt][nt][half * 2 + 0] + bia0;
                float v1 = acc[mt][nt][half * 2 + 1] + bia1;
                float2 o = make_float2(v0, v1);
                *(float2*)&Cf[(size_t)row * Ntot + col] = o;
            }
        }
    }
}

// ===================== fused per-head key MLP ==============================
// per 64-row tile of kact (remapped rows):
//   h1 = gelu(kact @ W1^T + b1)  (64x128, kept in smem hi/lo)
//   ka = elu(h1 @ W2^T + b2) + 1 (64x64 fp32 -> gmem)
__global__ void __launch_bounds__(256, 2)
mlp_fused(const h16* __restrict__ kh, const h16* __restrict__ kl,
          const h16* __restrict__ W1, const h16* __restrict__ W2,
          const float* __restrict__ b1, const float* __restrict__ b2,
          float* __restrict__ ka) {
    extern __shared__ char sm[];
    // A1h @0 (8K), A1l @8192, W1 @16384 (16K), A2h @32768 (2x8K khalf),
    // A2l @49152, W2 @65536 (2x8K khalf). total 80K
    const int tid = threadIdx.x;
    const int lane = tid & 31, wid = tid >> 5;
    const int wm = wid >> 2, wn4 = wid & 3;
    const int row0 = blockIdx.x * 64;
    const uint32_t smb = smem_u32(sm);

    // ---- loads ----
#pragma unroll
    for (int i = 0; i < 2; i++) {
        int idx = tid + i * 256;
        int r = idx >> 3, u = idx & 7;
        uint32_t so = SWZ128((uint32_t)(r * 128 + u * 16));
        cp_async16(smb + so, kh + (size_t)(row0 + r) * 64 + u * 8);
        cp_async16(smb + 8192 + so, kl + (size_t)(row0 + r) * 64 + u * 8);
    }
#pragma unroll
    for (int i = 0; i < 4; i++) {
        int idx = tid + i * 256;
        int r = idx >> 3, u = idx & 7;
        cp_async16(smb + 16384 + SWZ128((uint32_t)(r * 128 + u * 16)),
                   W1 + r * 64 + u * 8);
    }
#pragma unroll
    for (int i = 0; i < 4; i++) {
        int idx = tid + i * 256;
        int n = idx >> 4, u = idx & 15;
        int khf = u >> 3, u2 = u & 7;
        cp_async16(smb + 65536 + khf * 8192 + SWZ128((uint32_t)(n * 128 + u2 * 16)),
                   W2 + n * 128 + u * 8);
    }
    CP_COMMIT();
    CP_WAIT0();
    __syncthreads();

    // ---- GEMM1: 64x128x64 ----
    float acc1[2][4][4];
#pragma unroll
    for (int i = 0; i < 2; i++)
#pragma unroll
        for (int j = 0; j < 4; j++)
#pragma unroll
            for (int t = 0; t < 4; t++) acc1[i][j][t] = 0.f;

#pragma unroll
    for (int ks = 0; ks < 4; ks++) {
        uint32_t ah[2][4], al[2][4], bb[4][2];
#pragma unroll
        for (int mt = 0; mt < 2; mt++) {
            int row = wm * 32 + mt * 16 + (lane & 15);
            int kb = ks * 32 + ((lane >> 4) << 4);
            uint32_t so = SWZ128((uint32_t)(row * 128 + kb));
            ldmatrix_x4(smb + so, ah[mt][0], ah[mt][1], ah[mt][2], ah[mt][3]);
            ldmatrix_x4(smb + 8192 + so, al[mt][0], al[mt][1], al[mt][2],
                        al[mt][3]);
        }
#pragma unroll
        for (int p = 0; p < 2; p++) {
            int row = wn4 * 32 + p * 16 + ((lane >> 4) << 3) + (lane & 7);
            int kb = ks * 32 + (((lane & 15) >> 3) << 4);
            ldmatrix_x4(smb + 16384 + SWZ128((uint32_t)(row * 128 + kb)),
                        bb[2 * p][0], bb[2 * p][1], bb[2 * p + 1][0],
                        bb[2 * p + 1][1]);
        }
#pragma unroll
        for (int mt = 0; mt < 2; mt++)
#pragma unroll
            for (int nt = 0; nt < 4; nt++) mma16816(acc1[mt][nt], ah[mt], bb[nt]);
#pragma unroll
        for (int mt = 0; mt < 2; mt++)
#pragma unroll
            for (int nt = 0; nt < 4; nt++) mma16816(acc1[mt][nt], al[mt], bb[nt]);
    }

    // ---- epilogue1: gelu + split -> A2 smem ----
#pragma unroll
    for (int mt = 0; mt < 2; mt++) {
#pragma unroll
        for (int nt = 0; nt < 4; nt++) {
            int col = wn4 * 32 + nt * 8 + 2 * (lane & 3);
            float bia0 = b1[col], bia1 = b1[col + 1];
            int khf = col >> 6, cc = col & 63;
#pragma unroll
            for (int half = 0; half < 2; half++) {
                int row = wm * 32 + mt * 16 + (lane >> 2) + half * 8;
                float v0 = acc1[mt][nt][half * 2 + 0] + bia0;
                float v1 = acc1[mt][nt][half * 2 + 1] + bia1;
                v0 = 0.5f * v0 * (1.f + erff(v0 * 0.70710678118654752f));
                v1 = 0.5f * v1 * (1.f + erff(v1 * 0.70710678118654752f));
                h16 h0 = __float2half(v0), h1v = __float2half(v1);
                h16 l0 = __float2half(v0 - __half2float(h0));
                h16 l1 = __float2half(v1 - __half2float(h1v));
                h162 ph; ph.x = h0; ph.y = h1v;
                h162 pl; pl.x = l0; pl.y = l1;
                uint32_t off = 32768 + khf * 8192 +
                               SWZ128((uint32_t)(row * 128 + cc * 2));
                *(h162*)(sm + off) = ph;
                *(h162*)(sm + off + 16384) = pl;
            }
        }
    }
    __syncthreads();

    // ---- GEMM2: 64x64x128 ----
    float acc2[2][2][4];
#pragma unroll
    for (int i = 0; i < 2; i++)
#pragma unroll
        for (int j = 0; j < 2; j++)
#pragma unroll
            for (int t = 0; t < 4; t++) acc2[i][j][t] = 0.f;

#pragma unroll
    for (int kstep = 0; kstep < 8; kstep++) {
        int khf = kstep >> 2, ks2 = kstep & 3;
        uint32_t ah[2][4], al[2][4], bb[2][2];
#pragma unroll
        for (int mt = 0; mt < 2; mt++) {
            int row = wm * 32 + mt * 16 + (lane & 15);
            int kb = ks2 * 32 + ((lane >> 4) << 4);
            uint32_t so = SWZ128((uint32_t)(row * 128 + kb));
            ldmatrix_x4(smb + 32768 + khf * 8192 + so,
                        ah[mt][0], ah[mt][1], ah[mt][2], ah[mt][3]);
            ldmatrix_x4(smb + 49152 + khf * 8192 + so,
                        al[mt][0], al[mt][1], al[mt][2], al[mt][3]);
        }
        {
            int row = wn4 * 16 + ((lane >> 4) << 3) + (lane & 7);
            int kb = ks2 * 32 + (((lane & 15) >> 3) << 4);
            ldmatrix_x4(smb + 65536 + khf * 8192 +
                            SWZ128((uint32_t)(row * 128 + kb)),
                        bb[0][0], bb[0][1], bb[1][0], bb[1][1]);
        }
#pragma unroll
        for (int mt = 0; mt < 2; mt++)
#pragma unroll
            for (int nt = 0; nt < 2; nt++) mma16816(acc2[mt][nt], ah[mt], bb[nt]);
#pragma unroll
        for (int mt = 0; mt < 2; mt++)
#pragma unroll
            for (int nt = 0; nt < 2; nt++) mma16816(acc2[mt][nt], al[mt], bb[nt]);
    }

    // ---- epilogue2: elu+1 -> ka fp32 ----
#pragma unroll
    for (int mt = 0; mt < 2; mt++) {
#pragma unroll
        for (int nt = 0; nt < 2; nt++) {
            int col = wn4 * 16 + nt * 8 + 2 * (lane & 3);
            float bia0 = b2[col], bia1 = b2[col + 1];
#pragma unroll
            for (int half = 0; half < 2; half++) {
                int row = wm * 32 + mt * 16 + (lane >> 2) + half * 8;
                float v0 = acc2[mt][nt][half * 2 + 0] + bia0;
                float v1 = acc2[mt][nt][half * 2 + 1] + bia1;
                v0 = (v0 > 0.f) ? (v0 + 1.f) : expf(v0);
                v1 = (v1 > 0.f) ? (v1 + 1.f) : expf(v1);
                float2 o = make_float2(v0, v1);
                *(float2*)&ka[(size_t)(row0 + row) * 64 + col] = o;
            }
        }
    }
}

// ===================== zero =====================
__global__ void zero_kernel(float* __restrict__ kv, float* __restrict__ ksum) {
    int i = blockIdx.x * blockDim.x + threadIdx.x;
    if (i < BB * HH * DD * DD) kv[i] = 0.f;
    if (i < BB * HH * DD) ksum[i] = 0.f;
}

// ===================== kv context (fused ksum) =====================
__global__ void kv_kernel(const float* __restrict__ ka, const float* __restrict__ v,
                          float* __restrict__ kv, float* __restrict__ ksum) {
    const int bh = blockIdx.x;
    const int b = bh / HH, h = bh % HH;
    const int m0 = blockIdx.y * 256;
    __shared__ float ka_s[16][64];
    __shared__ float v_s[16][64];
    const int tid = threadIdx.x;
    const int tx = tid % 16, ty = tid / 16;
    float acc[4][4];
    float ksm[4] = {0.f, 0.f, 0.f, 0.f};
#pragma unroll
    for (int i = 0; i < 4; i++)
#pragma unroll
        for (int j = 0; j < 4; j++) acc[i][j] = 0.f;
    const size_t vbase = (size_t)b * MMCTX * EE + (size_t)h * DD;
    for (int mt = 0; mt < 16; mt++) {
        const int m = m0 + mt * 16;
        {
            int mm = tid / 16, e4 = tid % 16;
            // ka rows are remapped: ((b*M + m)*H + h)
            size_t karow = ((size_t)b * MMCTX + m + mm) * HH + h;
            float4 kav = *(const float4*)&ka[karow * 64 + e4 * 4];
            *(float4*)&ka_s[mm][e4 * 4] = kav;
            ksm[0] += kav.x; ksm[1] += kav.y; ksm[2] += kav.z; ksm[3] += kav.w;
            *(float4*)&v_s[mm][e4 * 4] = *(const float4*)&v[vbase + (size_t)(m + mm) * EE + e4 * 4];
        }
        __syncthreads();
#pragma unroll
        for (int mm = 0; mm < 16; mm++) {
            float rd[4];
            float4 re = *(const float4*)&v_s[mm][tx * 4];
#pragma unroll
            for (int i = 0; i < 4; i++) rd[i] = ka_s[mm][ty * 4 + i];
#pragma unroll
            for (int i = 0; i < 4; i++) {
                acc[i][0] += rd[i] * re.x; acc[i][1] += rd[i] * re.y;
                acc[i][2] += rd[i] * re.z; acc[i][3] += rd[i] * re.w;
            }
        }
        __syncthreads();
    }
    const float inv_m = 1.f / (float)MMCTX;
#pragma unroll
    for (int i = 0; i < 4; i++)
#pragma unroll
        for (int j = 0; j < 4; j++)
            atomicAdd(&kv[((size_t)bh * DD + ty * 4 + i) * DD + tx * 4 + j],
                      acc[i][j] * inv_m);
    {
        int e4 = tid % 16;
#pragma unroll
        for (int j = 0; j < 4; j++)
            atomicAdd(&ksum[bh * DD + e4 * 4 + j], ksm[j] * inv_m);
    }
}

// ===================== out einsum + normalize -> attn hi/lo ================
#define OUT_ROWS 32
__global__ void out_kernel(const float* __restrict__ q, const float* __restrict__ kv,
                           const float* __restrict__ ksum,
                           h16* __restrict__ attn_h, h16* __restrict__ attn_l) {
    extern __shared__ float smf[];
    float* kv_s = smf;
    float* ks_s = smf + HH * DD * DD;
    const int b = blockIdx.x;
    const int r0 = blockIdx.y * OUT_ROWS;
    const int tid = threadIdx.x;
    for (int i = tid; i < HH * DD * DD / 4; i += 256)
        *(float4*)&kv_s[i * 4] = *(const float4*)&kv[(size_t)b * HH * DD * DD + i * 4];
    for (int i = tid; i < HH * DD / 4; i += 256)
        *(float4*)&ks_s[i * 4] = *(const float4*)&ksum[b * HH * DD + i * 4];
    __syncthreads();
    const int h = tid / 32, lane = tid % 32;
    const float* kvh = &kv_s[h * DD * DD];
    for (int r = 0; r < OUT_ROWS; r++) {
        const int n = r0 + r;
        const size_t row = (size_t)b * NN + n;
        const size_t qb = row * EE + h * DD;
        float q0 = q[qb + lane];
        float q1 = q[qb + lane + 32];
        float dp = q0 * ks_s[h * DD + lane] + q1 * ks_s[h * DD + lane + 32];
#pragma unroll
        for (int off = 16; off; off >>= 1) dp += __shfl_xor_sync(0xffffffffu, dp, off);
        dp = fmaxf(dp, 1e-6f);
        float a0 = 0.f, a1 = 0.f;
#pragma unroll
        for (int d = 0; d < DD; d++) {
            float qd = __shfl_sync(0xffffffffu, (d < 32) ? q0 : q1, d & 31);
            float2 kvv = *(const float2*)&kvh[d * DD + lane * 2];
            a0 += qd * kvv.x;
            a1 += qd * kvv.y;
        }
        a0 /= dp; a1 /= dp;
        a0 = isnan(a0) ? 0.f : fminf(fmaxf(a0, -65000.f), 65000.f);
        a1 = isnan(a1) ? 0.f : fminf(fmaxf(a1, -65000.f), 65000.f);
        h16 h0 = __float2half(a0), h1 = __float2half(a1);
        h16 l0 = __float2half(a0 - __half2float(h0));
        h16 l1 = __float2half(a1 - __half2float(h1));
        h162 ph; ph.x = h0; ph.y = h1;
        h162 pl; pl.x = l0; pl.y = l1;
        *(h162*)&attn_h[qb + lane * 2] = ph;
        *(h162*)&attn_l[qb + lane * 2] = pl;
    }
}

// ===================== launch =====================
extern "C" void kernel_launch(void* const* d_in, const int* in_sizes, int n_in,
                              void* d_out, int out_size) {
    const float* query = (const float*)d_in[0];
    const float* key   = (const float*)d_in[1];
    const float* value = (const float*)d_in[2];
    const float* Wq = (const float*)d_in[3];
    const float* bq = (const float*)d_in[4];
    const float* Wk = (const float*)d_in[5];
    const float* bk = (const float*)d_in[6];
    const float* Wv = (const float*)d_in[7];
    const float* bv = (const float*)d_in[8];
    const float* W1 = (const float*)d_in[9];
    const float* b1 = (const float*)d_in[10];
    const float* W2 = (const float*)d_in[11];
    const float* b2 = (const float*)d_in[12];
    const float* Wo = (const float*)d_in[13];
    const float* bo = (const float*)d_in[14];
    float* out = (float*)d_out;

    float *q_s, *v_s, *ka_s, *kv_s, *ksum_s;
    cudaGetSymbolAddress((void**)&q_s, g_q);
    cudaGetSymbolAddress((void**)&v_s, g_v);
    cudaGetSymbolAddress((void**)&ka_s, g_ka);
    cudaGetSymbolAddress((void**)&kv_s, g_kv);
    cudaGetSymbolAddress((void**)&ksum_s, g_ksum);

    h16 *kact_h, *kact_l, *attn_h, *attn_l;
    h16 *Wqd, *Wkd, *Wvd, *Wod, *W1d, *W2d;
    cudaGetSymbolAddress((void**)&kact_h, g_kact_h);
    cudaGetSymbolAddress((void**)&kact_l, g_kact_l);
    cudaGetSymbolAddress((void**)&attn_h, g_attn_h);
    cudaGetSymbolAddress((void**)&attn_l, g_attn_l);
    cudaGetSymbolAddress((void**)&Wqd, g_Wq);
    cudaGetSymbolAddress((void**)&Wkd, g_Wk);
    cudaGetSymbolAddress((void**)&Wvd, g_Wv);
    cudaGetSymbolAddress((void**)&Wod, g_Wo);
    cudaGetSymbolAddress((void**)&W1d, g_W1);
    cudaGetSymbolAddress((void**)&W2d, g_W2);

    const int SMF = 81920;
    const int SM2 = 98304;
    const int SMM = 81920;
    cudaFuncSetAttribute((const void*)mma_gemmF<1, 0>,
                         cudaFuncAttributeMaxDynamicSharedMemorySize, SMF);
    cudaFuncSetAttribute((const void*)mma_gemmF<1, 1>,
                         cudaFuncAttributeMaxDynamicSharedMemorySize, SMF);
    cudaFuncSetAttribute((const void*)mma_gemmF<0, 0>,
                         cudaFuncAttributeMaxDynamicSharedMemorySize, SMF);
    cudaFuncSetAttribute((const void*)mma_gemm2,
                         cudaFuncAttributeMaxDynamicSharedMemorySize, SM2);
    cudaFuncSetAttribute((const void*)mlp_fused,
                         cudaFuncAttributeMaxDynamicSharedMemorySize, SMM);

    // ---- weight conversions (small)
    conv_wt<<<(EE * EE + 255) / 256, 256>>>(Wq, Wqd, EE, EE);
    conv_wt<<<(EE * EE + 255) / 256, 256>>>(Wk, Wkd, EE, EE);
    conv_wt<<<(EE * EE + 255) / 256, 256>>>(Wv, Wvd, EE, EE);
    conv_wt<<<(EE * EE + 255) / 256, 256>>>(Wo, Wod, EE, EE);
    conv_wt<<<(64 * 128 + 255) / 256, 256>>>(W1, W1d, 64, 128);
    conv_wt<<<(128 * 64 + 255) / 256, 256>>>(W2, W2d, 128, 64);
    {
        int nz = BB * HH * DD * DD;
        zero_kernel<<<(nz + 255) / 256, 256>>>(kv_s, ksum_s);
    }

    // ---- projections (conversion fused into GEMM)
    {
        dim3 grid(EE / 128, ROWS_QK / 128);
        mma_gemmF<1, 0><<<grid, 256, SMF>>>(query, Wqd, bq, q_s, nullptr,
                                            nullptr, EE, EE, 0);
        mma_gemmF<1, 1><<<grid, 256, SMF>>>(key, Wkd, bk, nullptr, kact_h,
                                            kact_l, EE, EE, 64);
        mma_gemmF<0, 0><<<grid, 256, SMF>>>(value, Wvd, bv, v_s, nullptr,
                                            nullptr, EE, EE, 0);
    }
    // ---- fused key MLP
    mlp_fused<<<ROWS_MLP / 64, 256, SMM>>>(kact_h, kact_l, W1d, W2d, b1, b2,
                                           ka_s);
    // ---- kv context + fused ksum
    {
        dim3 gkv(BB * HH, MMCTX / 256);
        kv_kernel<<<gkv, 256>>>(ka_s, v_s, kv_s, ksum_s);
    }
    // ---- out einsum + normalize -> attn hi/lo
    {
        size_t smem = (size_t)(HH * DD * DD + HH * DD) * sizeof(float);
        cudaFuncSetAttribute(out_kernel, cudaFuncAttributeMaxDynamicSharedMemorySize,
                             (int)smem);
        dim3 go(BB, NN / OUT_ROWS);
        out_kernel<<<go, 256, smem>>>(q_s, kv_s, ksum_s, attn_h, attn_l);
    }
    // ---- final projection
    {
        dim3 grid(EE / 128, ROWS_QK / 128);
        mma_gemm2<<<grid, 256, SM2>>>(attn_h, attn_l, Wod, bo, out, EE, EE);
    }
}

// round 8
// speedup vs baseline: 3.4595x; 1.2929x over previous
#include <cuda_runtime.h>
#include <cuda_fp16.h>
#include <math.h>
#include <stdint.h>

#define BB 4
#define NN 4096
#define MMCTX 4096
#define EE 512
#define HH 8
#define DD 64
#define ROWS_QK (BB * NN)          // 16384
#define ROWS_MLP (BB * MMCTX * HH) // 131072

typedef __half h16;
typedef __half2 h162;

__device__ __forceinline__ uint32_t smem_u32(const void* p) {
    uint32_t a;
    asm("{ .reg .u64 t; cvta.to.shared.u64 t, %1; cvt.u32.u64 %0, t; }"
        : "=r"(a) : "l"(p));
    return a;
}

#define SWZ128(b) ((b) ^ (((b) >> 3) & 0x70))

__device__ __forceinline__ void cp_async16(uint32_t dst, const void* src) {
    asm volatile("cp.async.cg.shared.global [%0], [%1], 16;\n"
                 :: "r"(dst), "l"(src));
}
#define CP_COMMIT() asm volatile("cp.async.commit_group;\n" ::: "memory")
#define CP_WAIT1() asm volatile("cp.async.wait_group 1;\n" ::: "memory")
#define CP_WAIT0() asm volatile("cp.async.wait_group 0;\n" ::: "memory")

__device__ __forceinline__ void ldmatrix_x4(uint32_t addr, uint32_t& r0,
                                            uint32_t& r1, uint32_t& r2,
                                            uint32_t& r3) {
    asm volatile("ldmatrix.sync.aligned.m8n8.x4.shared.b16 {%0,%1,%2,%3}, [%4];"
                 : "=r"(r0), "=r"(r1), "=r"(r2), "=r"(r3) : "r"(addr));
}

__device__ __forceinline__ void mma16816(float* c, const uint32_t* a,
                                         const uint32_t* b) {
    asm volatile(
        "mma.sync.aligned.m16n8k16.row.col.f32.f16.f16.f32 "
        "{%0,%1,%2,%3}, {%4,%5,%6,%7}, {%8,%9}, {%0,%1,%2,%3};"
        : "+f"(c[0]), "+f"(c[1]), "+f"(c[2]), "+f"(c[3])
        : "r"(a[0]), "r"(a[1]), "r"(a[2]), "r"(a[3]), "r"(b[0]), "r"(b[1]));
}

// ===================== scratch =====================
__device__ float g_q[ROWS_QK * EE];
__device__ float g_v[ROWS_QK * EE];
__device__ float g_ka[ROWS_MLP * DD];
__device__ float g_kv[BB * HH * DD * DD];
__device__ float g_ksum[BB * HH * DD];

__device__ h16 g_kact[ROWS_MLP * DD];
__device__ h16 g_attn[ROWS_QK * EE];

__device__ h16 g_Wq[EE * EE];
__device__ h16 g_Wk[EE * EE];
__device__ h16 g_Wv[EE * EE];
__device__ h16 g_Wo[EE * EE];
__device__ h16 g_W1[128 * 64];
__device__ h16 g_W2[64 * 128];

// ===================== weight conversion (tiled transpose) =================
// W[k*N+n] (fp32) -> o[n*K+k] (fp16), coalesced read and write
__global__ void conv_wt(const float* __restrict__ W, h16* __restrict__ o,
                        int K, int N) {
    __shared__ float t[32][33];
    const int n0 = blockIdx.x * 32, k0 = blockIdx.y * 32;
    const int tx = threadIdx.x, ty = threadIdx.y;  // 32 x 8
#pragma unroll
    for (int i = 0; i < 4; i++)
        t[ty + i * 8][tx] = W[(size_t)(k0 + ty + i * 8) * N + n0 + tx];
    __syncthreads();
#pragma unroll
    for (int i = 0; i < 4; i++)
        o[(size_t)(n0 + ty + i * 8) * K + k0 + tx] =
            __float2half(t[tx][ty + i * 8]);
}

__device__ __forceinline__ float apply_epi(float v, int EPI) {
    if (EPI == 1) return (v > 0.f) ? (v + 1.f) : expf(v);
    if (EPI == 2) return 0.5f * v * (1.f + erff(v * 0.70710678118654752f));
    return v;
}

// ===================== converting fp32-A HMMA GEMM (BN=128, BK=32) =========
// C = epi(A @ W^T + bias): A fp32 [M,K]; B fp16 [N,K]. fp32->fp16 in-kernel.
// OUTM: 0 -> Cf fp32 [M,Ntot]; 1 -> Ch fp16, row remap chunk CK.
template <int EPI, int OUTM>
__global__ void __launch_bounds__(256, 2)
mma_gemmF(const float* __restrict__ A, const h16* __restrict__ B,
          const float* __restrict__ bias, float* __restrict__ Cf,
          h16* __restrict__ Ch, int Ntot, int K, int CK) {
    extern __shared__ char sm[];
    // layout: A32 2x16K @0 ; B 2x16K @32768 ; conv fp16 16K @65536
    const int tid = threadIdx.x;
    const int lane = tid & 31, wid = tid >> 5;
    const int wm = wid >> 1, wn = wid & 1;
    const int row0 = blockIdx.y * 128;
    const int col0 = blockIdx.x * 128;
    const uint32_t smb = smem_u32(sm);
    const int nc = K / 32;

    float acc[2][8][4];
#pragma unroll
    for (int i = 0; i < 2; i++)
#pragma unroll
        for (int j = 0; j < 8; j++)
#pragma unroll
            for (int t = 0; t < 4; t++) acc[i][j][t] = 0.f;

    auto load_stage = [&](int c, int buf) {
        uint32_t as = smb + buf * 16384;
        uint32_t bs = smb + 32768 + buf * 16384;
        const float* Ap = A + (size_t)row0 * K + c * 32;
        const h16* Bp = B + (size_t)col0 * K + c * 32;
#pragma unroll
        for (int i = 0; i < 4; i++) {
            int idx = tid + i * 256;
            int r = idx >> 3, u = idx & 7;
            cp_async16(as + SWZ128((uint32_t)(r * 128 + u * 16)),
                       Ap + (size_t)r * K + u * 4);
        }
#pragma unroll
        for (int i = 0; i < 2; i++) {
            int idx = tid + i * 256;
            int r = idx >> 2, u = idx & 3;
            cp_async16(bs + SWZ128((uint32_t)(r * 128 + u * 16)),
                       Bp + (size_t)r * K + u * 8);
        }
    };

    load_stage(0, 0);
    CP_COMMIT();

    for (int c = 0; c < nc; c++) {
        if (c + 1 < nc) {
            load_stage(c + 1, (c + 1) & 1);
            CP_COMMIT();
            CP_WAIT1();
        } else {
            CP_WAIT0();
        }
        // convert own segs: A32[c&1] fp32 -> fp16
        {
            char* ap = sm + (c & 1) * 16384;
            char* cvp = sm + 65536;
#pragma unroll
            for (int i = 0; i < 4; i++) {
                int idx = tid + i * 256;
                int r = idx >> 3, u = idx & 7;
                float4 v4 = *(const float4*)(ap + SWZ128((uint32_t)(r * 128 + u * 16)));
                h162 p0; p0.x = __float2half(v4.x); p0.y = __float2half(v4.y);
                h162 p1; p1.x = __float2half(v4.z); p1.y = __float2half(v4.w);
                uint32_t d = SWZ128((uint32_t)(r * 128 + u * 8));
                *(h162*)(cvp + d) = p0;
                *(h162*)(cvp + d + 4) = p1;
            }
        }
        __syncthreads();
        const uint32_t cvb = smb + 65536;
        const uint32_t bsb = smb + 32768 + (c & 1) * 16384;
#pragma unroll
        for (int ks = 0; ks < 2; ks++) {
            uint32_t ah[2][4], bb[8][2];
#pragma unroll
            for (int mt = 0; mt < 2; mt++) {
                int row = wm * 32 + mt * 16 + (lane & 15);
                int kb = ks * 32 + ((lane >> 4) << 4);
                ldmatrix_x4(cvb + SWZ128((uint32_t)(row * 128 + kb)),
                            ah[mt][0], ah[mt][1], ah[mt][2], ah[mt][3]);
            }
#pragma unroll
            for (int p = 0; p < 4; p++) {
                int row = wn * 64 + p * 16 + ((lane >> 4) << 3) + (lane & 7);
                int kb = ks * 32 + (((lane & 15) >> 3) << 4);
                ldmatrix_x4(bsb + SWZ128((uint32_t)(row * 128 + kb)),
                            bb[2 * p][0], bb[2 * p][1], bb[2 * p + 1][0],
                            bb[2 * p + 1][1]);
            }
#pragma unroll
            for (int mt = 0; mt < 2; mt++)
#pragma unroll
                for (int nt = 0; nt < 8; nt++) mma16816(acc[mt][nt], ah[mt], bb[nt]);
        }
        __syncthreads();
    }

    // ---- epilogue ----
    const int EPR = (OUTM == 1) ? (Ntot / CK) : 1;
#pragma unroll
    for (int mt = 0; mt < 2; mt++) {
#pragma unroll
        for (int nt = 0; nt < 8; nt++) {
            int col = col0 + wn * 64 + nt * 8 + 2 * (lane & 3);
            float bia0 = bias[col], bia1 = bias[col + 1];
#pragma unroll
            for (int half = 0; half < 2; half++) {
                int row = row0 + wm * 32 + mt * 16 + (lane >> 2) + half * 8;
                float v0 = apply_epi(acc[mt][nt][half * 2 + 0] + bia0, EPI);
                float v1 = apply_epi(acc[mt][nt][half * 2 + 1] + bia1, EPI);
                if (OUTM == 0) {
                    float2 o = make_float2(v0, v1);
                    *(float2*)&Cf[(size_t)row * Ntot + col] = o;
                } else {
                    int rp = row * EPR + col / CK;
                    int cp = col % CK;
                    h162 ph; ph.x = __float2half(v0); ph.y = __float2half(v1);
                    *(h162*)&Ch[(size_t)rp * CK + cp] = ph;
                }
            }
        }
    }
}

// ===================== fp16 HMMA GEMM (attn @ Wo) ==========================
__global__ void __launch_bounds__(256, 2)
mma_gemmH(const h16* __restrict__ A, const h16* __restrict__ B,
          const float* __restrict__ bias, float* __restrict__ Cf, int Ntot,
          int K) {
    extern __shared__ char sm[];
    constexpr int STAGE = 2 * 16384;  // A 16K + B 16K
    const int tid = threadIdx.x;
    const int lane = tid & 31, wid = tid >> 5;
    const int wm = wid >> 1, wn = wid & 1;
    const int row0 = blockIdx.y * 128;
    const int col0 = blockIdx.x * 128;
    const uint32_t smb = smem_u32(sm);
    const int nc = K / 64;

    float acc[2][8][4];
#pragma unroll
    for (int i = 0; i < 2; i++)
#pragma unroll
        for (int j = 0; j < 8; j++)
#pragma unroll
            for (int t = 0; t < 4; t++) acc[i][j][t] = 0.f;

    auto load_stage = [&](int c, int buf) {
        uint32_t as = smb + buf * STAGE;
        uint32_t bs = as + 16384;
        const h16* Ap = A + (size_t)row0 * K + c * 64;
        const h16* Bp = B + (size_t)col0 * K + c * 64;
#pragma unroll
        for (int i = 0; i < 4; i++) {
            int idx = tid + i * 256;
            int r = idx >> 3, u = idx & 7;
            uint32_t so = SWZ128((uint32_t)(r * 128 + u * 16));
            cp_async16(as + so, Ap + (size_t)r * K + u * 8);
            cp_async16(bs + so, Bp + (size_t)r * K + u * 8);
        }
    };

    load_stage(0, 0);
    CP_COMMIT();

    for (int c = 0; c < nc; c++) {
        if (c + 1 < nc) {
            load_stage(c + 1, (c + 1) & 1);
            CP_COMMIT();
            CP_WAIT1();
        } else {
            CP_WAIT0();
        }
        __syncthreads();
        uint32_t as = smb + (c & 1) * STAGE;
        uint32_t bs = as + 16384;
#pragma unroll
        for (int ks = 0; ks < 4; ks++) {
            uint32_t ah[2][4], bb[8][2];
#pragma unroll
            for (int mt = 0; mt < 2; mt++) {
                int row = wm * 32 + mt * 16 + (lane & 15);
                int kb = ks * 32 + ((lane >> 4) << 4);
                ldmatrix_x4(as + SWZ128((uint32_t)(row * 128 + kb)),
                            ah[mt][0], ah[mt][1], ah[mt][2], ah[mt][3]);
            }
#pragma unroll
            for (int p = 0; p < 4; p++) {
                int row = wn * 64 + p * 16 + ((lane >> 4) << 3) + (lane & 7);
                int kb = ks * 32 + (((lane & 15) >> 3) << 4);
                ldmatrix_x4(bs + SWZ128((uint32_t)(row * 128 + kb)),
                            bb[2 * p][0], bb[2 * p][1], bb[2 * p + 1][0],
                            bb[2 * p + 1][1]);
            }
#pragma unroll
            for (int mt = 0; mt < 2; mt++)
#pragma unroll
                for (int nt = 0; nt < 8; nt++) mma16816(acc[mt][nt], ah[mt], bb[nt]);
        }
        __syncthreads();
    }

#pragma unroll
    for (int mt = 0; mt < 2; mt++) {
#pragma unroll
        for (int nt = 0; nt < 8; nt++) {
            int col = col0 + wn * 64 + nt * 8 + 2 * (lane & 3);
            float bia0 = bias[col], bia1 = bias[col + 1];
#pragma unroll
            for (int half = 0; half < 2; half++) {
                int row = row0 + wm * 32 + mt * 16 + (lane >> 2) + half * 8;
                float v0 = acc[mt][nt][half * 2 + 0] + bia0;
                float v1 = acc[mt][nt][half * 2 + 1] + bia1;
                float2 o = make_float2(v0, v1);
                *(float2*)&Cf[(size_t)row * Ntot + col] = o;
            }
        }
    }
}

// ===================== fused per-head key MLP ==============================
// per 64-row tile: h1 = gelu(kact @ W1^T + b1) in smem; ka = elu(h1 @ W2^T)+1
__global__ void __launch_bounds__(256, 2)
mlp_fused(const h16* __restrict__ kin, const h16* __restrict__ W1,
          const h16* __restrict__ W2, const float* __restrict__ b1,
          const float* __restrict__ b2, float* __restrict__ ka) {
    extern __shared__ char sm[];
    // A1 @0 (8K), W1 @8192 (16K), A2 @24576 (2x8K), W2 @40960 (2x8K). 56K
    const int tid = threadIdx.x;
    const int lane = tid & 31, wid = tid >> 5;
    const int wm = wid >> 2, wn4 = wid & 3;
    const int row0 = blockIdx.x * 64;
    const uint32_t smb = smem_u32(sm);

#pragma unroll
    for (int i = 0; i < 2; i++) {
        int idx = tid + i * 256;
        int r = idx >> 3, u = idx & 7;
        cp_async16(smb + SWZ128((uint32_t)(r * 128 + u * 16)),
                   kin + (size_t)(row0 + r) * 64 + u * 8);
    }
#pragma unroll
    for (int i = 0; i < 4; i++) {
        int idx = tid + i * 256;
        int r = idx >> 3, u = idx & 7;
        cp_async16(smb + 8192 + SWZ128((uint32_t)(r * 128 + u * 16)),
                   W1 + r * 64 + u * 8);
    }
#pragma unroll
    for (int i = 0; i < 4; i++) {
        int idx = tid + i * 256;
        int n = idx >> 4, u = idx & 15;
        int khf = u >> 3, u2 = u & 7;
        cp_async16(smb + 40960 + khf * 8192 + SWZ128((uint32_t)(n * 128 + u2 * 16)),
                   W2 + n * 128 + u * 8);
    }
    CP_COMMIT();
    CP_WAIT0();
    __syncthreads();

    // ---- GEMM1: 64x128x64 ----
    float acc1[2][4][4];
#pragma unroll
    for (int i = 0; i < 2; i++)
#pragma unroll
        for (int j = 0; j < 4; j++)
#pragma unroll
            for (int t = 0; t < 4; t++) acc1[i][j][t] = 0.f;

#pragma unroll
    for (int ks = 0; ks < 4; ks++) {
        uint32_t ah[2][4], bb[4][2];
#pragma unroll
        for (int mt = 0; mt < 2; mt++) {
            int row = wm * 32 + mt * 16 + (lane & 15);
            int kb = ks * 32 + ((lane >> 4) << 4);
            ldmatrix_x4(smb + SWZ128((uint32_t)(row * 128 + kb)),
                        ah[mt][0], ah[mt][1], ah[mt][2], ah[mt][3]);
        }
#pragma unroll
        for (int p = 0; p < 2; p++) {
            int row = wn4 * 32 + p * 16 + ((lane >> 4) << 3) + (lane & 7);
            int kb = ks * 32 + (((lane & 15) >> 3) << 4);
            ldmatrix_x4(smb + 8192 + SWZ128((uint32_t)(row * 128 + kb)),
                        bb[2 * p][0], bb[2 * p][1], bb[2 * p + 1][0],
                        bb[2 * p + 1][1]);
        }
#pragma unroll
        for (int mt = 0; mt < 2; mt++)
#pragma unroll
            for (int nt = 0; nt < 4; nt++) mma16816(acc1[mt][nt], ah[mt], bb[nt]);
    }

    // ---- epilogue1: gelu -> A2 smem fp16 ----
#pragma unroll
    for (int mt = 0; mt < 2; mt++) {
#pragma unroll
        for (int nt = 0; nt < 4; nt++) {
            int col = wn4 * 32 + nt * 8 + 2 * (lane & 3);
            float bia0 = b1[col], bia1 = b1[col + 1];
            int khf = col >> 6, cc = col & 63;
#pragma unroll
            for (int half = 0; half < 2; half++) {
                int row = wm * 32 + mt * 16 + (lane >> 2) + half * 8;
                float v0 = acc1[mt][nt][half * 2 + 0] + bia0;
                float v1 = acc1[mt][nt][half * 2 + 1] + bia1;
                v0 = 0.5f * v0 * (1.f + erff(v0 * 0.70710678118654752f));
                v1 = 0.5f * v1 * (1.f + erff(v1 * 0.70710678118654752f));
                h162 ph; ph.x = __float2half(v0); ph.y = __float2half(v1);
                *(h162*)(sm + 24576 + khf * 8192 +
                         SWZ128((uint32_t)(row * 128 + cc * 2))) = ph;
            }
        }
    }
    __syncthreads();

    // ---- GEMM2: 64x64x128 ----
    float acc2[2][2][4];
#pragma unroll
    for (int i = 0; i < 2; i++)
#pragma unroll
        for (int j = 0; j < 2; j++)
#pragma unroll
            for (int t = 0; t < 4; t++) acc2[i][j][t] = 0.f;

#pragma unroll
    for (int kstep = 0; kstep < 8; kstep++) {
        int khf = kstep >> 2, ks2 = kstep & 3;
        uint32_t ah[2][4], bb[2][2];
#pragma unroll
        for (int mt = 0; mt < 2; mt++) {
            int row = wm * 32 + mt * 16 + (lane & 15);
            int kb = ks2 * 32 + ((lane >> 4) << 4);
            ldmatrix_x4(smb + 24576 + khf * 8192 +
                            SWZ128((uint32_t)(row * 128 + kb)),
                        ah[mt][0], ah[mt][1], ah[mt][2], ah[mt][3]);
        }
        {
            int row = wn4 * 16 + ((lane >> 4) << 3) + (lane & 7);
            int kb = ks2 * 32 + (((lane & 15) >> 3) << 4);
            ldmatrix_x4(smb + 40960 + khf * 8192 +
                            SWZ128((uint32_t)(row * 128 + kb)),
                        bb[0][0], bb[0][1], bb[1][0], bb[1][1]);
        }
#pragma unroll
        for (int mt = 0; mt < 2; mt++)
#pragma unroll
            for (int nt = 0; nt < 2; nt++) mma16816(acc2[mt][nt], ah[mt], bb[nt]);
    }

    // ---- epilogue2: elu+1 -> ka fp32 ----
#pragma unroll
    for (int mt = 0; mt < 2; mt++) {
#pragma unroll
        for (int nt = 0; nt < 2; nt++) {
            int col = wn4 * 16 + nt * 8 + 2 * (lane & 3);
            float bia0 = b2[col], bia1 = b2[col + 1];
#pragma unroll
            for (int half = 0; half < 2; half++) {
                int row = wm * 32 + mt * 16 + (lane >> 2) + half * 8;
                float v0 = acc2[mt][nt][half * 2 + 0] + bia0;
                float v1 = acc2[mt][nt][half * 2 + 1] + bia1;
                v0 = (v0 > 0.f) ? (v0 + 1.f) : expf(v0);
                v1 = (v1 > 0.f) ? (v1 + 1.f) : expf(v1);
                float2 o = make_float2(v0, v1);
                *(float2*)&ka[(size_t)(row0 + row) * 64 + col] = o;
            }
        }
    }
}

// ===================== zero =====================
__global__ void zero_kernel(float* __restrict__ kv, float* __restrict__ ksum) {
    int i = blockIdx.x * blockDim.x + threadIdx.x;
    if (i < BB * HH * DD * DD) kv[i] = 0.f;
    if (i < BB * HH * DD) ksum[i] = 0.f;
}

// ===================== kv context (fused ksum) =====================
__global__ void kv_kernel(const float* __restrict__ ka, const float* __restrict__ v,
                          float* __restrict__ kv, float* __restrict__ ksum) {
    const int bh = blockIdx.x;
    const int b = bh / HH, h = bh % HH;
    const int m0 = blockIdx.y * 256;
    __shared__ float ka_s[16][64];
    __shared__ float v_s[16][64];
    const int tid = threadIdx.x;
    const int tx = tid % 16, ty = tid / 16;
    float acc[4][4];
    float ksm[4] = {0.f, 0.f, 0.f, 0.f};
#pragma unroll
    for (int i = 0; i < 4; i++)
#pragma unroll
        for (int j = 0; j < 4; j++) acc[i][j] = 0.f;
    const size_t vbase = (size_t)b * MMCTX * EE + (size_t)h * DD;
    for (int mt = 0; mt < 16; mt++) {
        const int m = m0 + mt * 16;
        {
            int mm = tid / 16, e4 = tid % 16;
            size_t karow = ((size_t)b * MMCTX + m + mm) * HH + h;
            float4 kav = *(const float4*)&ka[karow * 64 + e4 * 4];
            *(float4*)&ka_s[mm][e4 * 4] = kav;
            ksm[0] += kav.x; ksm[1] += kav.y; ksm[2] += kav.z; ksm[3] += kav.w;
            *(float4*)&v_s[mm][e4 * 4] =
                *(const float4*)&v[vbase + (size_t)(m + mm) * EE + e4 * 4];
        }
        __syncthreads();
#pragma unroll
        for (int mm = 0; mm < 16; mm++) {
            float rd[4];
            float4 re = *(const float4*)&v_s[mm][tx * 4];
#pragma unroll
            for (int i = 0; i < 4; i++) rd[i] = ka_s[mm][ty * 4 + i];
#pragma unroll
            for (int i = 0; i < 4; i++) {
                acc[i][0] += rd[i] * re.x; acc[i][1] += rd[i] * re.y;
                acc[i][2] += rd[i] * re.z; acc[i][3] += rd[i] * re.w;
            }
        }
        __syncthreads();
    }
    const float inv_m = 1.f / (float)MMCTX;
#pragma unroll
    for (int i = 0; i < 4; i++)
#pragma unroll
        for (int j = 0; j < 4; j++)
            atomicAdd(&kv[((size_t)bh * DD + ty * 4 + i) * DD + tx * 4 + j],
                      acc[i][j] * inv_m);
    {
        int e4 = tid % 16;
#pragma unroll
        for (int j = 0; j < 4; j++)
            atomicAdd(&ksum[bh * DD + e4 * 4 + j], ksm[j] * inv_m);
    }
}

// ===================== out einsum + normalize -> attn fp16 =================
#define OUT_ROWS 32
__global__ void out_kernel(const float* __restrict__ q, const float* __restrict__ kv,
                           const float* __restrict__ ksum,
                           h16* __restrict__ attn) {
    extern __shared__ float smf[];
    float* kv_s = smf;
    float* ks_s = smf + HH * DD * DD;
    const int b = blockIdx.x;
    const int r0 = blockIdx.y * OUT_ROWS;
    const int tid = threadIdx.x;
    for (int i = tid; i < HH * DD * DD / 4; i += 256)
        *(float4*)&kv_s[i * 4] = *(const float4*)&kv[(size_t)b * HH * DD * DD + i * 4];
    for (int i = tid; i < HH * DD / 4; i += 256)
        *(float4*)&ks_s[i * 4] = *(const float4*)&ksum[b * HH * DD + i * 4];
    __syncthreads();
    const int h = tid / 32, lane = tid % 32;
    const float* kvh = &kv_s[h * DD * DD];
    for (int r = 0; r < OUT_ROWS; r++) {
        const int n = r0 + r;
        const size_t row = (size_t)b * NN + n;
        const size_t qb = row * EE + h * DD;
        float q0 = q[qb + lane];
        float q1 = q[qb + lane + 32];
        float dp = q0 * ks_s[h * DD + lane] + q1 * ks_s[h * DD + lane + 32];
#pragma unroll
        for (int off = 16; off; off >>= 1) dp += __shfl_xor_sync(0xffffffffu, dp, off);
        dp = fmaxf(dp, 1e-6f);
        float a0 = 0.f, a1 = 0.f;
#pragma unroll
        for (int d = 0; d < DD; d++) {
            float qd = __shfl_sync(0xffffffffu, (d < 32) ? q0 : q1, d & 31);
            float2 kvv = *(const float2*)&kvh[d * DD + lane * 2];
            a0 += qd * kvv.x;
            a1 += qd * kvv.y;
        }
        a0 /= dp; a1 /= dp;
        a0 = isnan(a0) ? 0.f : fminf(fmaxf(a0, -65000.f), 65000.f);
        a1 = isnan(a1) ? 0.f : fminf(fmaxf(a1, -65000.f), 65000.f);
        h162 ph; ph.x = __float2half(a0); ph.y = __float2half(a1);
        *(h162*)&attn[qb + lane * 2] = ph;
    }
}

// ===================== launch =====================
extern "C" void kernel_launch(void* const* d_in, const int* in_sizes, int n_in,
                              void* d_out, int out_size) {
    const float* query = (const float*)d_in[0];
    const float* key   = (const float*)d_in[1];
    const float* value = (const float*)d_in[2];
    const float* Wq = (const float*)d_in[3];
    const float* bq = (const float*)d_in[4];
    const float* Wk = (const float*)d_in[5];
    const float* bk = (const float*)d_in[6];
    const float* Wv = (const float*)d_in[7];
    const float* bv = (const float*)d_in[8];
    const float* W1 = (const float*)d_in[9];
    const float* b1 = (const float*)d_in[10];
    const float* W2 = (const float*)d_in[11];
    const float* b2 = (const float*)d_in[12];
    const float* Wo = (const float*)d_in[13];
    const float* bo = (const float*)d_in[14];
    float* out = (float*)d_out;

    float *q_s, *v_s, *ka_s, *kv_s, *ksum_s;
    cudaGetSymbolAddress((void**)&q_s, g_q);
    cudaGetSymbolAddress((void**)&v_s, g_v);
    cudaGetSymbolAddress((void**)&ka_s, g_ka);
    cudaGetSymbolAddress((void**)&kv_s, g_kv);
    cudaGetSymbolAddress((void**)&ksum_s, g_ksum);

    h16 *kact, *attn, *Wqd, *Wkd, *Wvd, *Wod, *W1d, *W2d;
    cudaGetSymbolAddress((void**)&kact, g_kact);
    cudaGetSymbolAddress((void**)&attn, g_attn);
    cudaGetSymbolAddress((void**)&Wqd, g_Wq);
    cudaGetSymbolAddress((void**)&Wkd, g_Wk);
    cudaGetSymbolAddress((void**)&Wvd, g_Wv);
    cudaGetSymbolAddress((void**)&Wod, g_Wo);
    cudaGetSymbolAddress((void**)&W1d, g_W1);
    cudaGetSymbolAddress((void**)&W2d, g_W2);

    const int SMF = 81920;
    const int SMH = 65536;
    const int SMM = 57344;
    cudaFuncSetAttribute((const void*)mma_gemmF<1, 0>,
                         cudaFuncAttributeMaxDynamicSharedMemorySize, SMF);
    cudaFuncSetAttribute((const void*)mma_gemmF<1, 1>,
                         cudaFuncAttributeMaxDynamicSharedMemorySize, SMF);
    cudaFuncSetAttribute((const void*)mma_gemmF<0, 0>,
                         cudaFuncAttributeMaxDynamicSharedMemorySize, SMF);
    cudaFuncSetAttribute((const void*)mma_gemmH,
                         cudaFuncAttributeMaxDynamicSharedMemorySize, SMH);
    cudaFuncSetAttribute((const void*)mlp_fused,
                         cudaFuncAttributeMaxDynamicSharedMemorySize, SMM);

    // ---- weight conversions (tiled transpose, coalesced)
    {
        dim3 blk(32, 8);
        conv_wt<<<dim3(EE / 32, EE / 32), blk>>>(Wq, Wqd, EE, EE);
        conv_wt<<<dim3(EE / 32, EE / 32), blk>>>(Wk, Wkd, EE, EE);
        conv_wt<<<dim3(EE / 32, EE / 32), blk>>>(Wv, Wvd, EE, EE);
        conv_wt<<<dim3(EE / 32, EE / 32), blk>>>(Wo, Wod, EE, EE);
        conv_wt<<<dim3(128 / 32, 64 / 32), blk>>>(W1, W1d, 64, 128);
        conv_wt<<<dim3(64 / 32, 128 / 32), blk>>>(W2, W2d, 128, 64);
    }
    {
        int nz = BB * HH * DD * DD;
        zero_kernel<<<(nz + 255) / 256, 256>>>(kv_s, ksum_s);
    }

    // ---- projections (fp32->fp16 conversion fused into GEMM)
    {
        dim3 grid(EE / 128, ROWS_QK / 128);
        mma_gemmF<1, 0><<<grid, 256, SMF>>>(query, Wqd, bq, q_s, nullptr, EE,
                                            EE, 0);
        mma_gemmF<1, 1><<<grid, 256, SMF>>>(key, Wkd, bk, nullptr, kact, EE,
                                            EE, 64);
        mma_gemmF<0, 0><<<grid, 256, SMF>>>(value, Wvd, bv, v_s, nullptr, EE,
                                            EE, 0);
    }
    // ---- fused key MLP
    mlp_fused<<<ROWS_MLP / 64, 256, SMM>>>(kact, W1d, W2d, b1, b2, ka_s);
    // ---- kv context + fused ksum
    {
        dim3 gkv(BB * HH, MMCTX / 256);
        kv_kernel<<<gkv, 256>>>(ka_s, v_s, kv_s, ksum_s);
    }
    // ---- out einsum + normalize -> attn fp16
    {
        size_t smem = (size_t)(HH * DD * DD + HH * DD) * sizeof(float);
        cudaFuncSetAttribute(out_kernel, cudaFuncAttributeMaxDynamicSharedMemorySize,
                             (int)smem);
        dim3 go(BB, NN / OUT_ROWS);
        out_kernel<<<go, 256, smem>>>(q_s, kv_s, ksum_s, attn);
    }
    // ---- final projection
    {
        dim3 grid(EE / 128, ROWS_QK / 128);
        mma_gemmH<<<grid, 256, SMH>>>(attn, Wod, bo, out, EE, EE);
    }
}

// round 9
// speedup vs baseline: 3.5604x; 1.0292x over previous
#include <cuda_runtime.h>
#include <cuda_fp16.h>
#include <math.h>
#include <stdint.h>

#define BB 4
#define NN 4096
#define MMCTX 4096
#define EE 512
#define HH 8
#define DD 64
#define ROWS_QK (BB * NN)          // 16384
#define ROWS_MLP (BB * MMCTX * HH) // 131072

typedef __half h16;
typedef __half2 h162;

__device__ __forceinline__ uint32_t smem_u32(const void* p) {
    uint32_t a;
    asm("{ .reg .u64 t; cvta.to.shared.u64 t, %1; cvt.u32.u64 %0, t; }"
        : "=r"(a) : "l"(p));
    return a;
}

#define SWZ128(b) ((b) ^ (((b) >> 3) & 0x70))

__device__ __forceinline__ void cp_async16(uint32_t dst, const void* src) {
    asm volatile("cp.async.cg.shared.global [%0], [%1], 16;\n"
                 :: "r"(dst), "l"(src));
}
#define CP_COMMIT() asm volatile("cp.async.commit_group;\n" ::: "memory")
#define CP_WAIT1() asm volatile("cp.async.wait_group 1;\n" ::: "memory")
#define CP_WAIT0() asm volatile("cp.async.wait_group 0;\n" ::: "memory")

__device__ __forceinline__ void ldmatrix_x4(uint32_t addr, uint32_t& r0,
                                            uint32_t& r1, uint32_t& r2,
                                            uint32_t& r3) {
    asm volatile("ldmatrix.sync.aligned.m8n8.x4.shared.b16 {%0,%1,%2,%3}, [%4];"
                 : "=r"(r0), "=r"(r1), "=r"(r2), "=r"(r3) : "r"(addr));
}

__device__ __forceinline__ void mma16816(float* c, const uint32_t* a,
                                         const uint32_t* b) {
    asm volatile(
        "mma.sync.aligned.m16n8k16.row.col.f32.f16.f16.f32 "
        "{%0,%1,%2,%3}, {%4,%5,%6,%7}, {%8,%9}, {%0,%1,%2,%3};"
        : "+f"(c[0]), "+f"(c[1]), "+f"(c[2]), "+f"(c[3])
        : "r"(a[0]), "r"(a[1]), "r"(a[2]), "r"(a[3]), "r"(b[0]), "r"(b[1]));
}

// ===================== scratch =====================
__device__ h16 g_q16[ROWS_QK * EE];
__device__ h16 g_v16[ROWS_QK * EE];
__device__ h16 g_ka16[ROWS_MLP * DD];
__device__ float g_kv[BB * HH * DD * DD];
__device__ float g_ksum[BB * HH * DD];

__device__ h16 g_kact[ROWS_MLP * DD];
__device__ h16 g_attn[ROWS_QK * EE];

__device__ h16 g_Wq[EE * EE];
__device__ h16 g_Wk[EE * EE];
__device__ h16 g_Wv[EE * EE];
__device__ h16 g_Wo[EE * EE];
__device__ h16 g_W1[128 * 64];
__device__ h16 g_W2[64 * 128];

// ===================== weight conversion (4-way tiled transpose) ===========
__global__ void conv_wt4(const float* __restrict__ Wa, const float* __restrict__ Wb,
                         const float* __restrict__ Wc, const float* __restrict__ Wd,
                         h16* __restrict__ oa, h16* __restrict__ ob,
                         h16* __restrict__ oc, h16* __restrict__ od) {
    __shared__ float t[32][33];
    const float* W = (blockIdx.z == 0) ? Wa : (blockIdx.z == 1) ? Wb
                     : (blockIdx.z == 2) ? Wc : Wd;
    h16* o = (blockIdx.z == 0) ? oa : (blockIdx.z == 1) ? ob
             : (blockIdx.z == 2) ? oc : od;
    const int n0 = blockIdx.x * 32, k0 = blockIdx.y * 32;
    const int tx = threadIdx.x, ty = threadIdx.y;  // 32 x 8
#pragma unroll
    for (int i = 0; i < 4; i++)
        t[ty + i * 8][tx] = W[(size_t)(k0 + ty + i * 8) * EE + n0 + tx];
    __syncthreads();
#pragma unroll
    for (int i = 0; i < 4; i++)
        o[(size_t)(n0 + ty + i * 8) * EE + k0 + tx] =
            __float2half(t[tx][ty + i * 8]);
}

__global__ void conv_wt(const float* __restrict__ W, h16* __restrict__ o,
                        int K, int N) {
    __shared__ float t[32][33];
    const int n0 = blockIdx.x * 32, k0 = blockIdx.y * 32;
    const int tx = threadIdx.x, ty = threadIdx.y;
#pragma unroll
    for (int i = 0; i < 4; i++)
        t[ty + i * 8][tx] = W[(size_t)(k0 + ty + i * 8) * N + n0 + tx];
    __syncthreads();
#pragma unroll
    for (int i = 0; i < 4; i++)
        o[(size_t)(n0 + ty + i * 8) * K + k0 + tx] =
            __float2half(t[tx][ty + i * 8]);
}

__device__ __forceinline__ float apply_epi(float v, int EPI) {
    if (EPI == 1) return (v > 0.f) ? (v + 1.f) : expf(v);
    if (EPI == 2) return 0.5f * v * (1.f + erff(v * 0.70710678118654752f));
    return v;
}

// ===================== converting fp32-A HMMA GEMM (BN=128, BK=32) =========
// OUTM: 1 -> Ch fp16 row-remapped (chunk CK); 2 -> Ch fp16 plain [M,Ntot].
template <int EPI, int OUTM>
__global__ void __launch_bounds__(256, 2)
mma_gemmF(const float* __restrict__ A, const h16* __restrict__ B,
          const float* __restrict__ bias, h16* __restrict__ Ch, int Ntot,
          int K, int CK) {
    extern __shared__ char sm[];
    const int tid = threadIdx.x;
    const int lane = tid & 31, wid = tid >> 5;
    const int wm = wid >> 1, wn = wid & 1;
    const int row0 = blockIdx.y * 128;
    const int col0 = blockIdx.x * 128;
    const uint32_t smb = smem_u32(sm);
    const int nc = K / 32;

    float acc[2][8][4];
#pragma unroll
    for (int i = 0; i < 2; i++)
#pragma unroll
        for (int j = 0; j < 8; j++)
#pragma unroll
            for (int t = 0; t < 4; t++) acc[i][j][t] = 0.f;

    auto load_stage = [&](int c, int buf) {
        uint32_t as = smb + buf * 16384;
        uint32_t bs = smb + 32768 + buf * 16384;
        const float* Ap = A + (size_t)row0 * K + c * 32;
        const h16* Bp = B + (size_t)col0 * K + c * 32;
#pragma unroll
        for (int i = 0; i < 4; i++) {
            int idx = tid + i * 256;
            int r = idx >> 3, u = idx & 7;
            cp_async16(as + SWZ128((uint32_t)(r * 128 + u * 16)),
                       Ap + (size_t)r * K + u * 4);
        }
#pragma unroll
        for (int i = 0; i < 2; i++) {
            int idx = tid + i * 256;
            int r = idx >> 2, u = idx & 3;
            cp_async16(bs + SWZ128((uint32_t)(r * 128 + u * 16)),
                       Bp + (size_t)r * K + u * 8);
        }
    };

    load_stage(0, 0);
    CP_COMMIT();

    for (int c = 0; c < nc; c++) {
        if (c + 1 < nc) {
            load_stage(c + 1, (c + 1) & 1);
            CP_COMMIT();
            CP_WAIT1();
        } else {
            CP_WAIT0();
        }
        {
            char* ap = sm + (c & 1) * 16384;
            char* cvp = sm + 65536;
#pragma unroll
            for (int i = 0; i < 4; i++) {
                int idx = tid + i * 256;
                int r = idx >> 3, u = idx & 7;
                float4 v4 = *(const float4*)(ap + SWZ128((uint32_t)(r * 128 + u * 16)));
                h162 p0; p0.x = __float2half(v4.x); p0.y = __float2half(v4.y);
                h162 p1; p1.x = __float2half(v4.z); p1.y = __float2half(v4.w);
                uint32_t d = SWZ128((uint32_t)(r * 128 + u * 8));
                *(h162*)(cvp + d) = p0;
                *(h162*)(cvp + d + 4) = p1;
            }
        }
        __syncthreads();
        const uint32_t cvb = smb + 65536;
        const uint32_t bsb = smb + 32768 + (c & 1) * 16384;
#pragma unroll
        for (int ks = 0; ks < 2; ks++) {
            uint32_t ah[2][4], bb[8][2];
#pragma unroll
            for (int mt = 0; mt < 2; mt++) {
                int row = wm * 32 + mt * 16 + (lane & 15);
                int kb = ks * 32 + ((lane >> 4) << 4);
                ldmatrix_x4(cvb + SWZ128((uint32_t)(row * 128 + kb)),
                            ah[mt][0], ah[mt][1], ah[mt][2], ah[mt][3]);
            }
#pragma unroll
            for (int p = 0; p < 4; p++) {
                int row = wn * 64 + p * 16 + ((lane >> 4) << 3) + (lane & 7);
                int kb = ks * 32 + (((lane & 15) >> 3) << 4);
                ldmatrix_x4(bsb + SWZ128((uint32_t)(row * 128 + kb)),
                            bb[2 * p][0], bb[2 * p][1], bb[2 * p + 1][0],
                            bb[2 * p + 1][1]);
            }
#pragma unroll
            for (int mt = 0; mt < 2; mt++)
#pragma unroll
                for (int nt = 0; nt < 8; nt++) mma16816(acc[mt][nt], ah[mt], bb[nt]);
        }
        __syncthreads();
    }

    const int EPR = (OUTM == 1) ? (Ntot / CK) : 1;
#pragma unroll
    for (int mt = 0; mt < 2; mt++) {
#pragma unroll
        for (int nt = 0; nt < 8; nt++) {
            int col = col0 + wn * 64 + nt * 8 + 2 * (lane & 3);
            float bia0 = bias[col], bia1 = bias[col + 1];
#pragma unroll
            for (int half = 0; half < 2; half++) {
                int row = row0 + wm * 32 + mt * 16 + (lane >> 2) + half * 8;
                float v0 = apply_epi(acc[mt][nt][half * 2 + 0] + bia0, EPI);
                float v1 = apply_epi(acc[mt][nt][half * 2 + 1] + bia1, EPI);
                h162 ph; ph.x = __float2half(v0); ph.y = __float2half(v1);
                if (OUTM == 1) {
                    int rp = row * EPR + col / CK;
                    int cp = col % CK;
                    *(h162*)&Ch[(size_t)rp * CK + cp] = ph;
                } else {
                    *(h162*)&Ch[(size_t)row * Ntot + col] = ph;
                }
            }
        }
    }
}

// ===================== fp16 HMMA GEMM (attn @ Wo -> fp32 out) ==============
__global__ void __launch_bounds__(256, 2)
mma_gemmH(const h16* __restrict__ A, const h16* __restrict__ B,
          const float* __restrict__ bias, float* __restrict__ Cf, int Ntot,
          int K) {
    extern __shared__ char sm[];
    constexpr int STAGE = 2 * 16384;
    const int tid = threadIdx.x;
    const int lane = tid & 31, wid = tid >> 5;
    const int wm = wid >> 1, wn = wid & 1;
    const int row0 = blockIdx.y * 128;
    const int col0 = blockIdx.x * 128;
    const uint32_t smb = smem_u32(sm);
    const int nc = K / 64;

    float acc[2][8][4];
#pragma unroll
    for (int i = 0; i < 2; i++)
#pragma unroll
        for (int j = 0; j < 8; j++)
#pragma unroll
            for (int t = 0; t < 4; t++) acc[i][j][t] = 0.f;

    auto load_stage = [&](int c, int buf) {
        uint32_t as = smb + buf * STAGE;
        uint32_t bs = as + 16384;
        const h16* Ap = A + (size_t)row0 * K + c * 64;
        const h16* Bp = B + (size_t)col0 * K + c * 64;
#pragma unroll
        for (int i = 0; i < 4; i++) {
            int idx = tid + i * 256;
            int r = idx >> 3, u = idx & 7;
            uint32_t so = SWZ128((uint32_t)(r * 128 + u * 16));
            cp_async16(as + so, Ap + (size_t)r * K + u * 8);
            cp_async16(bs + so, Bp + (size_t)r * K + u * 8);
        }
    };

    load_stage(0, 0);
    CP_COMMIT();

    for (int c = 0; c < nc; c++) {
        if (c + 1 < nc) {
            load_stage(c + 1, (c + 1) & 1);
            CP_COMMIT();
            CP_WAIT1();
        } else {
            CP_WAIT0();
        }
        __syncthreads();
        uint32_t as = smb + (c & 1) * STAGE;
        uint32_t bs = as + 16384;
#pragma unroll
        for (int ks = 0; ks < 4; ks++) {
            uint32_t ah[2][4], bb[8][2];
#pragma unroll
            for (int mt = 0; mt < 2; mt++) {
                int row = wm * 32 + mt * 16 + (lane & 15);
                int kb = ks * 32 + ((lane >> 4) << 4);
                ldmatrix_x4(as + SWZ128((uint32_t)(row * 128 + kb)),
                            ah[mt][0], ah[mt][1], ah[mt][2], ah[mt][3]);
            }
#pragma unroll
            for (int p = 0; p < 4; p++) {
                int row = wn * 64 + p * 16 + ((lane >> 4) << 3) + (lane & 7);
                int kb = ks * 32 + (((lane & 15) >> 3) << 4);
                ldmatrix_x4(bs + SWZ128((uint32_t)(row * 128 + kb)),
                            bb[2 * p][0], bb[2 * p][1], bb[2 * p + 1][0],
                            bb[2 * p + 1][1]);
            }
#pragma unroll
            for (int mt = 0; mt < 2; mt++)
#pragma unroll
                for (int nt = 0; nt < 8; nt++) mma16816(acc[mt][nt], ah[mt], bb[nt]);
        }
        __syncthreads();
    }

#pragma unroll
    for (int mt = 0; mt < 2; mt++) {
#pragma unroll
        for (int nt = 0; nt < 8; nt++) {
            int col = col0 + wn * 64 + nt * 8 + 2 * (lane & 3);
            float bia0 = bias[col], bia1 = bias[col + 1];
#pragma unroll
            for (int half = 0; half < 2; half++) {
                int row = row0 + wm * 32 + mt * 16 + (lane >> 2) + half * 8;
                float v0 = acc[mt][nt][half * 2 + 0] + bia0;
                float v1 = acc[mt][nt][half * 2 + 1] + bia1;
                float2 o = make_float2(v0, v1);
                *(float2*)&Cf[(size_t)row * Ntot + col] = o;
            }
        }
    }
}

// ===================== fused per-head key MLP (128-row tiles) ==============
__global__ void __launch_bounds__(256, 2)
mlp_fused(const h16* __restrict__ kin, const h16* __restrict__ W1,
          const h16* __restrict__ W2, const float* __restrict__ b1,
          const float* __restrict__ b2, h16* __restrict__ ka) {
    extern __shared__ char sm[];
    // A1 @0 (16K), W1 @16384 (16K), A2 @32768 (2 khf x 16K), W2 @65536 (2x8K)
    const int tid = threadIdx.x;
    const int lane = tid & 31, wid = tid >> 5;
    const int wm = wid >> 2, wn4 = wid & 3;
    const int row0 = blockIdx.x * 128;
    const uint32_t smb = smem_u32(sm);

#pragma unroll
    for (int i = 0; i < 4; i++) {
        int idx = tid + i * 256;
        int r = idx >> 3, u = idx & 7;
        uint32_t so = SWZ128((uint32_t)(r * 128 + u * 16));
        cp_async16(smb + so, kin + (size_t)(row0 + r) * 64 + u * 8);
        cp_async16(smb + 16384 + so, W1 + r * 64 + u * 8);
    }
#pragma unroll
    for (int i = 0; i < 4; i++) {
        int idx = tid + i * 256;
        int n = idx >> 4, u = idx & 15;
        int khf = u >> 3, u2 = u & 7;
        cp_async16(smb + 65536 + khf * 8192 + SWZ128((uint32_t)(n * 128 + u2 * 16)),
                   W2 + n * 128 + u * 8);
    }
    CP_COMMIT();
    CP_WAIT0();
    __syncthreads();

    // ---- GEMM1: 128x128x64 ----
    float acc1[4][4][4];
#pragma unroll
    for (int i = 0; i < 4; i++)
#pragma unroll
        for (int j = 0; j < 4; j++)
#pragma unroll
            for (int t = 0; t < 4; t++) acc1[i][j][t] = 0.f;

#pragma unroll
    for (int ks = 0; ks < 4; ks++) {
        uint32_t ah[4][4], bb[4][2];
#pragma unroll
        for (int mt = 0; mt < 4; mt++) {
            int row = wm * 64 + mt * 16 + (lane & 15);
            int kb = ks * 32 + ((lane >> 4) << 4);
            ldmatrix_x4(smb + SWZ128((uint32_t)(row * 128 + kb)),
                        ah[mt][0], ah[mt][1], ah[mt][2], ah[mt][3]);
        }
#pragma unroll
        for (int p = 0; p < 2; p++) {
            int row = wn4 * 32 + p * 16 + ((lane >> 4) << 3) + (lane & 7);
            int kb = ks * 32 + (((lane & 15) >> 3) << 4);
            ldmatrix_x4(smb + 16384 + SWZ128((uint32_t)(row * 128 + kb)),
                        bb[2 * p][0], bb[2 * p][1], bb[2 * p + 1][0],
                        bb[2 * p + 1][1]);
        }
#pragma unroll
        for (int mt = 0; mt < 4; mt++)
#pragma unroll
            for (int nt = 0; nt < 4; nt++) mma16816(acc1[mt][nt], ah[mt], bb[nt]);
    }

    // ---- epilogue1: gelu -> A2 smem fp16 ----
#pragma unroll
    for (int mt = 0; mt < 4; mt++) {
#pragma unroll
        for (int nt = 0; nt < 4; nt++) {
            int col = wn4 * 32 + nt * 8 + 2 * (lane & 3);
            float bia0 = b1[col], bia1 = b1[col + 1];
            int khf = col >> 6, cc = col & 63;
#pragma unroll
            for (int half = 0; half < 2; half++) {
                int row = wm * 64 + mt * 16 + (lane >> 2) + half * 8;
                float v0 = acc1[mt][nt][half * 2 + 0] + bia0;
                float v1 = acc1[mt][nt][half * 2 + 1] + bia1;
                v0 = 0.5f * v0 * (1.f + erff(v0 * 0.70710678118654752f));
                v1 = 0.5f * v1 * (1.f + erff(v1 * 0.70710678118654752f));
                h162 ph; ph.x = __float2half(v0); ph.y = __float2half(v1);
                *(h162*)(sm + 32768 + khf * 16384 +
                         SWZ128((uint32_t)(row * 128 + cc * 2))) = ph;
            }
        }
    }
    __syncthreads();

    // ---- GEMM2: 128x64x128 ----
    float acc2[4][2][4];
#pragma unroll
    for (int i = 0; i < 4; i++)
#pragma unroll
        for (int j = 0; j < 2; j++)
#pragma unroll
            for (int t = 0; t < 4; t++) acc2[i][j][t] = 0.f;

#pragma unroll
    for (int kstep = 0; kstep < 8; kstep++) {
        int khf = kstep >> 2, ks2 = kstep & 3;
        uint32_t ah[4][4], bb[2][2];
#pragma unroll
        for (int mt = 0; mt < 4; mt++) {
            int row = wm * 64 + mt * 16 + (lane & 15);
            int kb = ks2 * 32 + ((lane >> 4) << 4);
            ldmatrix_x4(smb + 32768 + khf * 16384 +
                            SWZ128((uint32_t)(row * 128 + kb)),
                        ah[mt][0], ah[mt][1], ah[mt][2], ah[mt][3]);
        }
        {
            int row = wn4 * 16 + ((lane >> 4) << 3) + (lane & 7);
            int kb = ks2 * 32 + (((lane & 15) >> 3) << 4);
            ldmatrix_x4(smb + 65536 + khf * 8192 +
                            SWZ128((uint32_t)(row * 128 + kb)),
                        bb[0][0], bb[0][1], bb[1][0], bb[1][1]);
        }
#pragma unroll
        for (int mt = 0; mt < 4; mt++)
#pragma unroll
            for (int nt = 0; nt < 2; nt++) mma16816(acc2[mt][nt], ah[mt], bb[nt]);
    }

    // ---- epilogue2: elu+1 -> ka fp16 ----
#pragma unroll
    for (int mt = 0; mt < 4; mt++) {
#pragma unroll
        for (int nt = 0; nt < 2; nt++) {
            int col = wn4 * 16 + nt * 8 + 2 * (lane & 3);
            float bia0 = b2[col], bia1 = b2[col + 1];
#pragma unroll
            for (int half = 0; half < 2; half++) {
                int row = wm * 64 + mt * 16 + (lane >> 2) + half * 8;
                float v0 = acc2[mt][nt][half * 2 + 0] + bia0;
                float v1 = acc2[mt][nt][half * 2 + 1] + bia1;
                v0 = (v0 > 0.f) ? (v0 + 1.f) : expf(v0);
                v1 = (v1 > 0.f) ? (v1 + 1.f) : expf(v1);
                h162 ph; ph.x = __float2half(v0); ph.y = __float2half(v1);
                *(h162*)&ka[(size_t)(row0 + row) * 64 + col] = ph;
            }
        }
    }
}

// ===================== zero =====================
__global__ void zero_kernel(float* __restrict__ kv, float* __restrict__ ksum) {
    int i = blockIdx.x * blockDim.x + threadIdx.x;
    if (i < BB * HH * DD * DD) kv[i] = 0.f;
    if (i < BB * HH * DD) ksum[i] = 0.f;
}

// ===================== kv context (fp16 in, fused ksum) ====================
__global__ void kv_kernel(const h16* __restrict__ ka, const h16* __restrict__ v,
                          float* __restrict__ kv, float* __restrict__ ksum) {
    const int bh = blockIdx.x;
    const int b = bh / HH, h = bh % HH;
    const int m0 = blockIdx.y * 256;
    __shared__ float ka_s[16][64];
    __shared__ float v_s[16][64];
    const int tid = threadIdx.x;
    const int tx = tid % 16, ty = tid / 16;
    float acc[4][4];
    float ksm[4] = {0.f, 0.f, 0.f, 0.f};
#pragma unroll
    for (int i = 0; i < 4; i++)
#pragma unroll
        for (int j = 0; j < 4; j++) acc[i][j] = 0.f;
    const size_t vbase = (size_t)b * MMCTX * EE + (size_t)h * DD;
    for (int mt = 0; mt < 16; mt++) {
        const int m = m0 + mt * 16;
        {
            int mm = tid / 16, e4 = tid % 16;
            size_t karow = ((size_t)b * MMCTX + m + mm) * HH + h;
            uint2 kraw = *(const uint2*)&ka[karow * 64 + e4 * 4];
            h162 k0 = *reinterpret_cast<h162*>(&kraw.x);
            h162 k1 = *reinterpret_cast<h162*>(&kraw.y);
            float4 kav = make_float4(__half2float(k0.x), __half2float(k0.y),
                                     __half2float(k1.x), __half2float(k1.y));
            *(float4*)&ka_s[mm][e4 * 4] = kav;
            ksm[0] += kav.x; ksm[1] += kav.y; ksm[2] += kav.z; ksm[3] += kav.w;
            uint2 vraw = *(const uint2*)&v[vbase + (size_t)(m + mm) * EE + e4 * 4];
            h162 v0 = *reinterpret_cast<h162*>(&vraw.x);
            h162 v1 = *reinterpret_cast<h162*>(&vraw.y);
            float4 vv = make_float4(__half2float(v0.x), __half2float(v0.y),
                                    __half2float(v1.x), __half2float(v1.y));
            *(float4*)&v_s[mm][e4 * 4] = vv;
        }
        __syncthreads();
#pragma unroll
        for (int mm = 0; mm < 16; mm++) {
            float rd[4];
            float4 re = *(const float4*)&v_s[mm][tx * 4];
#pragma unroll
            for (int i = 0; i < 4; i++) rd[i] = ka_s[mm][ty * 4 + i];
#pragma unroll
            for (int i = 0; i < 4; i++) {
                acc[i][0] += rd[i] * re.x; acc[i][1] += rd[i] * re.y;
                acc[i][2] += rd[i] * re.z; acc[i][3] += rd[i] * re.w;
            }
        }
        __syncthreads();
    }
    const float inv_m = 1.f / (float)MMCTX;
#pragma unroll
    for (int i = 0; i < 4; i++)
#pragma unroll
        for (int j = 0; j < 4; j++)
            atomicAdd(&kv[((size_t)bh * DD + ty * 4 + i) * DD + tx * 4 + j],
                      acc[i][j] * inv_m);
    {
        int e4 = tid % 16;
#pragma unroll
        for (int j = 0; j < 4; j++)
            atomicAdd(&ksum[bh * DD + e4 * 4 + j], ksm[j] * inv_m);
    }
}

// ===================== out einsum + normalize (fp16 q) -> attn fp16 ========
#define OUT_ROWS 32
__global__ void out_kernel(const h16* __restrict__ q, const float* __restrict__ kv,
                           const float* __restrict__ ksum,
                           h16* __restrict__ attn) {
    extern __shared__ float smf[];
    float* kv_s = smf;
    float* ks_s = smf + HH * DD * DD;
    const int b = blockIdx.x;
    const int r0 = blockIdx.y * OUT_ROWS;
    const int tid = threadIdx.x;
    for (int i = tid; i < HH * DD * DD / 4; i += 256)
        *(float4*)&kv_s[i * 4] = *(const float4*)&kv[(size_t)b * HH * DD * DD + i * 4];
    for (int i = tid; i < HH * DD / 4; i += 256)
        *(float4*)&ks_s[i * 4] = *(const float4*)&ksum[b * HH * DD + i * 4];
    __syncthreads();
    const int h = tid / 32, lane = tid % 32;
    const float* kvh = &kv_s[h * DD * DD];
    for (int r = 0; r < OUT_ROWS; r++) {
        const int n = r0 + r;
        const size_t row = (size_t)b * NN + n;
        const size_t qb = row * EE + h * DD;
        float q0 = __half2float(q[qb + lane]);
        float q1 = __half2float(q[qb + lane + 32]);
        float dp = q0 * ks_s[h * DD + lane] + q1 * ks_s[h * DD + lane + 32];
#pragma unroll
        for (int off = 16; off; off >>= 1) dp += __shfl_xor_sync(0xffffffffu, dp, off);
        dp = fmaxf(dp, 1e-6f);
        float a0 = 0.f, a1 = 0.f;
#pragma unroll
        for (int d = 0; d < DD; d++) {
            float qd = __shfl_sync(0xffffffffu, (d < 32) ? q0 : q1, d & 31);
            float2 kvv = *(const float2*)&kvh[d * DD + lane * 2];
            a0 += qd * kvv.x;
            a1 += qd * kvv.y;
        }
        a0 /= dp; a1 /= dp;
        a0 = isnan(a0) ? 0.f : fminf(fmaxf(a0, -65000.f), 65000.f);
        a1 = isnan(a1) ? 0.f : fminf(fmaxf(a1, -65000.f), 65000.f);
        h162 ph; ph.x = __float2half(a0); ph.y = __float2half(a1);
        *(h162*)&attn[qb + lane * 2] = ph;
    }
}

// ===================== launch =====================
extern "C" void kernel_launch(void* const* d_in, const int* in_sizes, int n_in,
                              void* d_out, int out_size) {
    const float* query = (const float*)d_in[0];
    const float* key   = (const float*)d_in[1];
    const float* value = (const float*)d_in[2];
    const float* Wq = (const float*)d_in[3];
    const float* bq = (const float*)d_in[4];
    const float* Wk = (const float*)d_in[5];
    const float* bk = (const float*)d_in[6];
    const float* Wv = (const float*)d_in[7];
    const float* bv = (const float*)d_in[8];
    const float* W1 = (const float*)d_in[9];
    const float* b1 = (const float*)d_in[10];
    const float* W2 = (const float*)d_in[11];
    const float* b2 = (const float*)d_in[12];
    const float* Wo = (const float*)d_in[13];
    const float* bo = (const float*)d_in[14];
    float* out = (float*)d_out;

    float *kv_s, *ksum_s;
    cudaGetSymbolAddress((void**)&kv_s, g_kv);
    cudaGetSymbolAddress((void**)&ksum_s, g_ksum);

    h16 *q16, *v16, *ka16, *kact, *attn, *Wqd, *Wkd, *Wvd, *Wod, *W1d, *W2d;
    cudaGetSymbolAddress((void**)&q16, g_q16);
    cudaGetSymbolAddress((void**)&v16, g_v16);
    cudaGetSymbolAddress((void**)&ka16, g_ka16);
    cudaGetSymbolAddress((void**)&kact, g_kact);
    cudaGetSymbolAddress((void**)&attn, g_attn);
    cudaGetSymbolAddress((void**)&Wqd, g_Wq);
    cudaGetSymbolAddress((void**)&Wkd, g_Wk);
    cudaGetSymbolAddress((void**)&Wvd, g_Wv);
    cudaGetSymbolAddress((void**)&Wod, g_Wo);
    cudaGetSymbolAddress((void**)&W1d, g_W1);
    cudaGetSymbolAddress((void**)&W2d, g_W2);

    const int SMF = 81920;
    const int SMH = 65536;
    const int SMM = 81920;
    cudaFuncSetAttribute((const void*)mma_gemmF<1, 2>,
                         cudaFuncAttributeMaxDynamicSharedMemorySize, SMF);
    cudaFuncSetAttribute((const void*)mma_gemmF<1, 1>,
                         cudaFuncAttributeMaxDynamicSharedMemorySize, SMF);
    cudaFuncSetAttribute((const void*)mma_gemmF<0, 2>,
                         cudaFuncAttributeMaxDynamicSharedMemorySize, SMF);
    cudaFuncSetAttribute((const void*)mma_gemmH,
                         cudaFuncAttributeMaxDynamicSharedMemorySize, SMH);
    cudaFuncSetAttribute((const void*)mlp_fused,
                         cudaFuncAttributeMaxDynamicSharedMemorySize, SMM);

    // ---- weight conversions
    {
        dim3 blk(32, 8);
        conv_wt4<<<dim3(EE / 32, EE / 32, 4), blk>>>(Wq, Wk, Wv, Wo,
                                                     Wqd, Wkd, Wvd, Wod);
        conv_wt<<<dim3(128 / 32, 64 / 32), blk>>>(W1, W1d, 64, 128);
        conv_wt<<<dim3(64 / 32, 128 / 32), blk>>>(W2, W2d, 128, 64);
    }
    {
        int nz = BB * HH * DD * DD;
        zero_kernel<<<(nz + 255) / 256, 256>>>(kv_s, ksum_s);
    }

    // ---- projections
    {
        dim3 grid(EE / 128, ROWS_QK / 128);
        mma_gemmF<1, 2><<<grid, 256, SMF>>>(query, Wqd, bq, q16, EE, EE, 0);
        mma_gemmF<1, 1><<<grid, 256, SMF>>>(key, Wkd, bk, kact, EE, EE, 64);
        mma_gemmF<0, 2><<<grid, 256, SMF>>>(value, Wvd, bv, v16, EE, EE, 0);
    }
    // ---- fused key MLP (128-row tiles)
    mlp_fused<<<ROWS_MLP / 128, 256, SMM>>>(kact, W1d, W2d, b1, b2, ka16);
    // ---- kv context + fused ksum
    {
        dim3 gkv(BB * HH, MMCTX / 256);
        kv_kernel<<<gkv, 256>>>(ka16, v16, kv_s, ksum_s);
    }
    // ---- out einsum + normalize -> attn fp16
    {
        size_t smem = (size_t)(HH * DD * DD + HH * DD) * sizeof(float);
        cudaFuncSetAttribute(out_kernel, cudaFuncAttributeMaxDynamicSharedMemorySize,
                             (int)smem);
        dim3 go(BB, NN / OUT_ROWS);
        out_kernel<<<go, 256, smem>>>(q16, kv_s, ksum_s, attn);
    }
    // ---- final projection
    {
        dim3 grid(EE / 128, ROWS_QK / 128);
        mma_gemmH<<<grid, 256, SMH>>>(attn, Wod, bo, out, EE, EE);
    }
}